// round 3
// baseline (speedup 1.0000x reference)
#include <cuda_runtime.h>
#include <math.h>

#define BB 16
#define Nn 38
#define NTt 9
#define NEe 703
#define Rr 741
#define BRr (BB*Rr)
#define Ll 12

// ---------------- static device scratch ----------------
__device__ __align__(16) float  g_PS1[BB*Nn*384];
__device__ __align__(16) float  g_W2T[128*384];
__device__ __align__(16) float  g_W3T[128*384];
__device__ __align__(16) double g_EW1Td[Ll*384*128];
__device__ __align__(16) double g_NW1Td[Ll*128*128];
__device__ __align__(16) float  g_S[BRr*128];
__device__ __align__(16) float  g_sel2[BB*NEe*2*128];
__device__ double g_sum[128];
__device__ double g_sumsq[128];
__device__ double g_a[128];
__device__ double g_c0[128];
__device__ int    g_mode;

__device__ __forceinline__ bool read_mask(const void* p, int i, int mode) {
    if (mode == 0) return ((const unsigned char*)p)[i] != 0;
    if (mode == 1) return ((const float*)p)[i] != 0.0f;
    return ((const int*)p)[i] != 0;
}

__global__ void k_detect(const unsigned char* __restrict__ mn) {
    if (threadIdx.x == 0) {
        bool b8 = false, f32 = false;
        for (int i = 0; i < 152; i++) {
            unsigned char v = mn[i];
            if ((i & 3) != 0 && v == 1) b8 = true;
            if ((i & 3) == 3 && v == 0x3f) f32 = true;
        }
        g_mode = b8 ? 0 : (f32 ? 1 : 2);
    }
}

__global__ void k_zero() {
    int t = threadIdx.x;
    if (t < 128) { g_sum[t] = 0.0; g_sumsq[t] = 0.0; }
}

__global__ void k_prep_w(const float* __restrict__ gc2, const float* __restrict__ gc3,
                         const float* __restrict__ ew1, const float* __restrict__ nw1) {
    int i = blockIdx.x * 256 + threadIdx.x;
    if (i < 49152) {
        int k = i / 384, c = i % 384;
        g_W2T[i] = gc2[c*128 + k];
        g_W3T[i] = gc3[c*128 + k];
    }
    if (i < 589824) {
        int l = i / 49152, rem = i % 49152;
        int o = rem / 128, c = rem % 128;
        g_EW1Td[i] = (double)ew1[l*49152 + c*384 + o];
    }
    if (i < 196608) {
        int l = i / 16384, rem = i % 16384;
        int o = rem / 128, c = rem % 128;
        g_NW1Td[i] = (double)nw1[l*16384 + c*128 + o];
    }
}

__global__ void k_prep_ps1(const float* __restrict__ x, const float* __restrict__ embw,
                           const float* __restrict__ gc1) {
    __shared__ float h0[Nn*NTt];
    int b = blockIdx.x, t = threadIdx.x;
    if (t < Nn*NTt) {
        int j = t / NTt, tt = t % NTt;
        float acc = 0.f;
        #pragma unroll
        for (int u = 0; u < NTt; u++) acc += x[(b*Nn + j)*NTt + u] * embw[tt*NTt + u];
        h0[t] = acc;
    }
    __syncthreads();
    if (t < 384) {
        for (int j = 0; j < Nn; j++) {
            float acc = 0.f;
            #pragma unroll
            for (int u = 0; u < NTt; u++) acc += h0[j*NTt + u] * gc1[t*NTt + u];
            g_PS1[(b*Nn + j)*384 + t] = acc;
        }
    }
}

// out[i][o] = sum_{e,j} sA[e][i][j] * sS[j][e*128+o]
__device__ __forceinline__ void block_einsum(const float* __restrict__ sA,
                                             const float* __restrict__ sS,
                                             float* __restrict__ sH,
                                             int tx, int ty, bool relu) {
    float acc[5][4] = {};
    #pragma unroll
    for (int e = 0; e < 3; e++) {
        const float* aE = sA + e*1600 + ty*40;
        const float* sE = sS + e*128 + tx*4;
        for (int j = 0; j < Nn; j++) {
            float4 s4 = *(const float4*)(sE + j*384);
            #pragma unroll
            for (int ii = 0; ii < 5; ii++) {
                float a = aE[ii*320 + j];
                acc[ii][0] = fmaf(a, s4.x, acc[ii][0]);
                acc[ii][1] = fmaf(a, s4.y, acc[ii][1]);
                acc[ii][2] = fmaf(a, s4.z, acc[ii][2]);
                acc[ii][3] = fmaf(a, s4.w, acc[ii][3]);
            }
        }
    }
    #pragma unroll
    for (int ii = 0; ii < 5; ii++) {
        int i = ty + 8*ii;
        float4 v;
        v.x = relu ? fmaxf(acc[ii][0], 0.f) : acc[ii][0];
        v.y = relu ? fmaxf(acc[ii][1], 0.f) : acc[ii][1];
        v.z = relu ? fmaxf(acc[ii][2], 0.f) : acc[ii][2];
        v.w = relu ? fmaxf(acc[ii][3], 0.f) : acc[ii][3];
        *(float4*)(sH + i*128 + tx*4) = v;
    }
}

// sS[j][c] = sum_k sH[j][k] * WT[k][c]
__device__ __forceinline__ void block_gemm(const float* __restrict__ WT,
                                           const float* __restrict__ sH,
                                           float* __restrict__ sS,
                                           int tx, int ty) {
    #pragma unroll 1
    for (int cc = 0; cc < 3; cc++) {
        float acc[5][4] = {};
        const float* wb = WT + cc*128 + tx*4;
        const float* hb = sH + ty*128;
        #pragma unroll 4
        for (int k = 0; k < 128; k++) {
            float4 w4 = *(const float4*)(wb + k*384);
            #pragma unroll
            for (int jj = 0; jj < 5; jj++) {
                float h = hb[jj*1024 + k];
                acc[jj][0] = fmaf(h, w4.x, acc[jj][0]);
                acc[jj][1] = fmaf(h, w4.y, acc[jj][1]);
                acc[jj][2] = fmaf(h, w4.z, acc[jj][2]);
                acc[jj][3] = fmaf(h, w4.w, acc[jj][3]);
            }
        }
        float* ob = sS + cc*128 + tx*4;
        #pragma unroll
        for (int jj = 0; jj < 5; jj++) {
            int j = ty + 8*jj;
            if (j < Nn) {
                float4 v; v.x = acc[jj][0]; v.y = acc[jj][1]; v.z = acc[jj][2]; v.w = acc[jj][3];
                *(float4*)(ob + j*384) = v;
            }
        }
    }
}

__global__ __launch_bounds__(256) void k_rgcn(
    const float* __restrict__ adj, const void* __restrict__ maskn,
    const void* __restrict__ maske, const int* __restrict__ isel)
{
    extern __shared__ float sm[];
    float* sA = sm;            // 3*40*40
    float* sS = sm + 4800;     // 38*384
    float* sH = sm + 19392;    // 40*128
    int tid = threadIdx.x;
    int b = blockIdx.x / Rr, r = blockIdx.x % Rr;
    int mode = g_mode;

    for (int idx = tid; idx < 3*40*38; idx += 256) {
        int j = idx % 38;
        int i = (idx / 38) % 40;
        int e = idx / (38*40);
        float v = 0.f;
        if (i < Nn && read_mask(maske, r*1444 + i*38 + j, mode))
            v = adj[((b*4 + e)*38 + i)*38 + j];
        sA[e*1600 + i*40 + j] = v;
    }
    for (int idx = tid; idx < Nn*384; idx += 256) {
        int j = idx / 384;
        sS[idx] = read_mask(maskn, r*38 + j, mode) ? g_PS1[b*Nn*384 + idx] : 0.f;
    }
    __syncthreads();

    int tx = tid & 31, ty = tid >> 5;
    block_einsum(sA, sS, sH, tx, ty, true);   __syncthreads();
    block_gemm(g_W2T, sH, sS, tx, ty);        __syncthreads();
    block_einsum(sA, sS, sH, tx, ty, true);   __syncthreads();
    block_gemm(g_W3T, sH, sS, tx, ty);        __syncthreads();
    block_einsum(sA, sS, sH, tx, ty, false);  __syncthreads();

    if (tid < 128) {
        double s = 0.0, sq = 0.0;
        for (int i = 0; i < Nn; i++) {
            double v = (double)sH[i*128 + tid];
            s += v; sq += v*v;
        }
        g_S[blockIdx.x*128 + tid] = (float)s;
        atomicAdd(&g_sum[tid], s);
        atomicAdd(&g_sumsq[tid], sq);
    }
    if (r >= Nn) {
        int k = r - Nn;
        int o = tid & 127, sl = tid >> 7;
        int node = isel[k*2 + sl];
        g_sel2[((b*NEe + k)*2 + sl)*128 + o] = sH[node*128 + o];
    }
}

__global__ void k_stats(const float* __restrict__ gamma, const float* __restrict__ beta) {
    int o = threadIdx.x;
    if (o < 128) {
        const double cnt = (double)(BRr * Nn);
        double m   = g_sum[o] / cnt;
        double var = g_sumsq[o] / cnt - m*m;
        double inv = 1.0 / sqrt(var + 1e-5);
        double a = inv * (double)gamma[o];
        g_a[o]  = a;
        g_c0[o] = (double)beta[o] - m * a;
    }
}

__global__ __launch_bounds__(256) void k_node_flow(
    const float* __restrict__ x_deq, const float* __restrict__ nb1,
    const float* __restrict__ nw2, const float* __restrict__ nb2,
    float* __restrict__ out)
{
    __shared__ double sgw[8][128], shw[8][128], slw[8][9];
    int w = threadIdx.x >> 5, lane = threadIdx.x & 31;
    int row = blockIdx.x * 8 + w;
    if (row >= BB*Nn) return;
    int b = row / Nn, n = row % Nn;
    double* sg = sgw[w]; double* sh = shw[w]; double* sl = slw[w];
    #pragma unroll
    for (int q = 0; q < 4; q++) {
        int o = lane + 32*q;
        sg[o] = (double)g_S[(b*Rr + n)*128 + o] * g_a[o] + 38.0 * g_c0[o];
    }
    __syncwarp();
    int P = 0;
    for (int l = 0; l < Ll; l++) {
        const double* W1 = g_NW1Td + l*16384 + lane*4;
        double a0 = (double)nb1[l*128 + lane*4+0];
        double a1 = (double)nb1[l*128 + lane*4+1];
        double a2 = (double)nb1[l*128 + lane*4+2];
        double a3 = (double)nb1[l*128 + lane*4+3];
        for (int o = 0; o < 128; o++) {
            double s = sg[o];
            double2 wA = *(const double2*)(W1 + o*128);
            double2 wB = *(const double2*)(W1 + o*128 + 2);
            a0 = fma(s, wA.x, a0);
            a1 = fma(s, wA.y, a1);
            a2 = fma(s, wB.x, a2);
            a3 = fma(s, wB.y, a3);
        }
        sh[lane*4+0] = tanh(a0);
        sh[lane*4+1] = tanh(a1);
        sh[lane*4+2] = tanh(a2);
        sh[lane*4+3] = tanh(a3);
        __syncwarp();
        if (lane < NTt) {
            const float* W2 = nw2 + (l*NTt + lane)*128;
            double acc = (double)nb2[l*NTt + lane];
            for (int c = 0; c < 128; c++) acc = fma(sh[c], (double)W2[c], acc);
            sl[lane] = acc;
        }
        __syncwarp();
        double best = sl[0]; int bi = 0;
        #pragma unroll
        for (int t = 1; t < NTt; t++) { double v = sl[t]; if (v > best) { best = v; bi = t; } }
        P += bi;
        __syncwarp();
    }
    if (lane < NTt) {
        int p = P % NTt;
        out[row*NTt + lane] = x_deq[row*NTt + ((lane - p + 18) % NTt)];
    }
}

__global__ __launch_bounds__(256) void k_edge_flow(
    const float* __restrict__ adj_deq, const float* __restrict__ eb1,
    const float* __restrict__ ew2, const float* __restrict__ eb2,
    float* __restrict__ out)
{
    __shared__ double sgw[8][384], shw[8][128], slw[8][4];
    int w = threadIdx.x >> 5, lane = threadIdx.x & 31;
    int row = blockIdx.x * 8 + w;
    if (row >= BB*NEe) return;
    int b = row / NEe, k = row % NEe;
    double* sg = sgw[w]; double* sh = shw[w]; double* sl = slw[w];
    for (int idx = lane; idx < 384; idx += 32) {
        double v;
        if (idx < 256) {
            int o = idx & 127;
            v = (double)g_sel2[(b*NEe + k)*256 + idx] * g_a[o] + g_c0[o];
        } else {
            int o = idx - 256;
            v = (double)g_S[(b*Rr + Nn + k)*128 + o] * g_a[o] + 38.0 * g_c0[o];
        }
        sg[idx] = v;
    }
    __syncwarp();
    int P = 0;
    for (int l = 0; l < Ll; l++) {
        const double* W1 = g_EW1Td + l*49152 + lane*4;
        double a0 = (double)eb1[l*128 + lane*4+0];
        double a1 = (double)eb1[l*128 + lane*4+1];
        double a2 = (double)eb1[l*128 + lane*4+2];
        double a3 = (double)eb1[l*128 + lane*4+3];
        for (int o = 0; o < 384; o++) {
            double s = sg[o];
            double2 wA = *(const double2*)(W1 + o*128);
            double2 wB = *(const double2*)(W1 + o*128 + 2);
            a0 = fma(s, wA.x, a0);
            a1 = fma(s, wA.y, a1);
            a2 = fma(s, wB.x, a2);
            a3 = fma(s, wB.y, a3);
        }
        sh[lane*4+0] = tanh(a0);
        sh[lane*4+1] = tanh(a1);
        sh[lane*4+2] = tanh(a2);
        sh[lane*4+3] = tanh(a3);
        __syncwarp();
        if (lane < 4) {
            const float* W2 = ew2 + (l*4 + lane)*128;
            double acc = (double)eb2[l*4 + lane];
            for (int c = 0; c < 128; c++) acc = fma(sh[c], (double)W2[c], acc);
            sl[lane] = acc;
        }
        __syncwarp();
        double best = sl[0]; int bi = 0;
        if (sl[1] > best) { best = sl[1]; bi = 1; }
        if (sl[2] > best) { best = sl[2]; bi = 2; }
        if (sl[3] > best) { best = sl[3]; bi = 3; }
        P += bi;
        __syncwarp();
    }
    if (lane < 4) {
        int p = P & 3;
        out[BB*Nn*NTt + row*4 + lane] = adj_deq[row*4 + ((lane - p + 4) & 3)];
    }
}

extern "C" void kernel_launch(void* const* d_in, const int* in_sizes, int n_in,
                              void* d_out, int out_size) {
    const float* x       = (const float*)d_in[0];
    const float* adj     = (const float*)d_in[1];
    const float* x_deq   = (const float*)d_in[2];
    const float* adj_deq = (const float*)d_in[3];
    const void*  mn      = d_in[4];
    const void*  me      = d_in[5];
    const int*   isel    = (const int*)d_in[6];
    const float* embw    = (const float*)d_in[7];
    const float* gc1     = (const float*)d_in[8];
    const float* gc2     = (const float*)d_in[9];
    const float* gc3     = (const float*)d_in[10];
    const float* gamma   = (const float*)d_in[11];
    const float* beta    = (const float*)d_in[12];
    const float* nw1     = (const float*)d_in[13];
    const float* nb1     = (const float*)d_in[14];
    const float* nw2     = (const float*)d_in[15];
    const float* nb2     = (const float*)d_in[16];
    const float* ew1     = (const float*)d_in[17];
    const float* eb1     = (const float*)d_in[18];
    const float* ew2     = (const float*)d_in[19];
    const float* eb2     = (const float*)d_in[20];
    float* out = (float*)d_out;

    cudaFuncSetAttribute(k_rgcn, cudaFuncAttributeMaxDynamicSharedMemorySize, 98304);

    k_detect<<<1, 32>>>((const unsigned char*)mn);
    k_zero<<<1, 128>>>();
    k_prep_w<<<2304, 256>>>(gc2, gc3, ew1, nw1);
    k_prep_ps1<<<16, 384>>>(x, embw, gc1);
    k_rgcn<<<BRr, 256, 98048>>>(adj, mn, me, isel);
    k_stats<<<1, 128>>>(gamma, beta);
    k_node_flow<<<76, 256>>>(x_deq, nb1, nw2, nb2, out);
    k_edge_flow<<<1406, 256>>>(adj_deq, eb1, ew2, eb2, out);
}

// round 4
// speedup vs baseline: 1.4163x; 1.4163x over previous
#include <cuda_runtime.h>
#include <math.h>

#define BB 16
#define Nn 38
#define NTt 9
#define NEe 703
#define Rr 741
#define BRr (BB*Rr)
#define Ll 12
#define EROWS (BB*NEe)   // 11248
#define NROWS (BB*Nn)    // 608

// ---------------- static device scratch ----------------
__device__ __align__(16) float  g_PS1[BB*Nn*384];
__device__ __align__(16) float  g_W2T[128*384];
__device__ __align__(16) float  g_W3T[128*384];
__device__ __align__(16) float  g_EW1T[Ll*384*128];  // [l][o][c]
__device__ __align__(16) float  g_NW1T[Ll*128*128];  // [l][o][c]
__device__ __align__(16) float  g_S[BRr*128];
__device__ __align__(16) float  g_sel2[BB*NEe*2*128];
__device__ double g_sum[128];
__device__ double g_sumsq[128];
__device__ double g_a[128];
__device__ double g_c0[128];
__device__ int    g_mode;

__device__ __forceinline__ bool read_mask(const void* p, int i, int mode) {
    if (mode == 0) return ((const unsigned char*)p)[i] != 0;
    if (mode == 1) return ((const float*)p)[i] != 0.0f;
    return ((const int*)p)[i] != 0;
}

__global__ void k_detect(const unsigned char* __restrict__ mn) {
    if (threadIdx.x == 0) {
        bool b8 = false, f32 = false;
        for (int i = 0; i < 152; i++) {
            unsigned char v = mn[i];
            if ((i & 3) != 0 && v == 1) b8 = true;
            if ((i & 3) == 3 && v == 0x3f) f32 = true;
        }
        g_mode = b8 ? 0 : (f32 ? 1 : 2);
    }
}

__global__ void k_zero() {
    int t = threadIdx.x;
    if (t < 128) { g_sum[t] = 0.0; g_sumsq[t] = 0.0; }
}

__global__ void k_prep_w(const float* __restrict__ gc2, const float* __restrict__ gc3,
                         const float* __restrict__ ew1, const float* __restrict__ nw1) {
    int i = blockIdx.x * 256 + threadIdx.x;
    if (i < 49152) {
        int k = i / 384, c = i % 384;
        g_W2T[i] = gc2[c*128 + k];
        g_W3T[i] = gc3[c*128 + k];
    }
    if (i < 589824) {
        int l = i / 49152, rem = i % 49152;
        int o = rem / 128, c = rem % 128;
        g_EW1T[i] = ew1[l*49152 + c*384 + o];
    }
    if (i < 196608) {
        int l = i / 16384, rem = i % 16384;
        int o = rem / 128, c = rem % 128;
        g_NW1T[i] = nw1[l*16384 + c*128 + o];
    }
}

__global__ void k_prep_ps1(const float* __restrict__ x, const float* __restrict__ embw,
                           const float* __restrict__ gc1) {
    __shared__ float h0[Nn*NTt];
    int b = blockIdx.x, t = threadIdx.x;
    if (t < Nn*NTt) {
        int j = t / NTt, tt = t % NTt;
        float acc = 0.f;
        #pragma unroll
        for (int u = 0; u < NTt; u++) acc += x[(b*Nn + j)*NTt + u] * embw[tt*NTt + u];
        h0[t] = acc;
    }
    __syncthreads();
    if (t < 384) {
        for (int j = 0; j < Nn; j++) {
            float acc = 0.f;
            #pragma unroll
            for (int u = 0; u < NTt; u++) acc += h0[j*NTt + u] * gc1[t*NTt + u];
            g_PS1[(b*Nn + j)*384 + t] = acc;
        }
    }
}

// ---------------- fused RGCN (unchanged from passing R2) ----------------
__device__ __forceinline__ void block_einsum(const float* __restrict__ sA,
                                             const float* __restrict__ sS,
                                             float* __restrict__ sH,
                                             int tx, int ty, bool relu) {
    float acc[5][4] = {};
    #pragma unroll
    for (int e = 0; e < 3; e++) {
        const float* aE = sA + e*1600 + ty*40;
        const float* sE = sS + e*128 + tx*4;
        for (int j = 0; j < Nn; j++) {
            float4 s4 = *(const float4*)(sE + j*384);
            #pragma unroll
            for (int ii = 0; ii < 5; ii++) {
                float a = aE[ii*320 + j];
                acc[ii][0] = fmaf(a, s4.x, acc[ii][0]);
                acc[ii][1] = fmaf(a, s4.y, acc[ii][1]);
                acc[ii][2] = fmaf(a, s4.z, acc[ii][2]);
                acc[ii][3] = fmaf(a, s4.w, acc[ii][3]);
            }
        }
    }
    #pragma unroll
    for (int ii = 0; ii < 5; ii++) {
        int i = ty + 8*ii;
        float4 v;
        v.x = relu ? fmaxf(acc[ii][0], 0.f) : acc[ii][0];
        v.y = relu ? fmaxf(acc[ii][1], 0.f) : acc[ii][1];
        v.z = relu ? fmaxf(acc[ii][2], 0.f) : acc[ii][2];
        v.w = relu ? fmaxf(acc[ii][3], 0.f) : acc[ii][3];
        *(float4*)(sH + i*128 + tx*4) = v;
    }
}

__device__ __forceinline__ void block_gemm(const float* __restrict__ WT,
                                           const float* __restrict__ sH,
                                           float* __restrict__ sS,
                                           int tx, int ty) {
    #pragma unroll 1
    for (int cc = 0; cc < 3; cc++) {
        float acc[5][4] = {};
        const float* wb = WT + cc*128 + tx*4;
        const float* hb = sH + ty*128;
        #pragma unroll 4
        for (int k = 0; k < 128; k++) {
            float4 w4 = *(const float4*)(wb + k*384);
            #pragma unroll
            for (int jj = 0; jj < 5; jj++) {
                float h = hb[jj*1024 + k];
                acc[jj][0] = fmaf(h, w4.x, acc[jj][0]);
                acc[jj][1] = fmaf(h, w4.y, acc[jj][1]);
                acc[jj][2] = fmaf(h, w4.z, acc[jj][2]);
                acc[jj][3] = fmaf(h, w4.w, acc[jj][3]);
            }
        }
        float* ob = sS + cc*128 + tx*4;
        #pragma unroll
        for (int jj = 0; jj < 5; jj++) {
            int j = ty + 8*jj;
            if (j < Nn) {
                float4 v; v.x = acc[jj][0]; v.y = acc[jj][1]; v.z = acc[jj][2]; v.w = acc[jj][3];
                *(float4*)(ob + j*384) = v;
            }
        }
    }
}

__global__ __launch_bounds__(256) void k_rgcn(
    const float* __restrict__ adj, const void* __restrict__ maskn,
    const void* __restrict__ maske, const int* __restrict__ isel)
{
    extern __shared__ float sm[];
    float* sA = sm;            // 3*40*40
    float* sS = sm + 4800;     // 38*384
    float* sH = sm + 19392;    // 40*128
    int tid = threadIdx.x;
    int b = blockIdx.x / Rr, r = blockIdx.x % Rr;
    int mode = g_mode;

    for (int idx = tid; idx < 3*40*38; idx += 256) {
        int j = idx % 38;
        int i = (idx / 38) % 40;
        int e = idx / (38*40);
        float v = 0.f;
        if (i < Nn && read_mask(maske, r*1444 + i*38 + j, mode))
            v = adj[((b*4 + e)*38 + i)*38 + j];
        sA[e*1600 + i*40 + j] = v;
    }
    for (int idx = tid; idx < Nn*384; idx += 256) {
        int j = idx / 384;
        sS[idx] = read_mask(maskn, r*38 + j, mode) ? g_PS1[b*Nn*384 + idx] : 0.f;
    }
    __syncthreads();

    int tx = tid & 31, ty = tid >> 5;
    block_einsum(sA, sS, sH, tx, ty, true);   __syncthreads();
    block_gemm(g_W2T, sH, sS, tx, ty);        __syncthreads();
    block_einsum(sA, sS, sH, tx, ty, true);   __syncthreads();
    block_gemm(g_W3T, sH, sS, tx, ty);        __syncthreads();
    block_einsum(sA, sS, sH, tx, ty, false);  __syncthreads();

    if (tid < 128) {
        double s = 0.0, sq = 0.0;
        for (int i = 0; i < Nn; i++) {
            double v = (double)sH[i*128 + tid];
            s += v; sq += v*v;
        }
        g_S[blockIdx.x*128 + tid] = (float)s;
        atomicAdd(&g_sum[tid], s);
        atomicAdd(&g_sumsq[tid], sq);
    }
    if (r >= Nn) {
        int k = r - Nn;
        int o = tid & 127, sl = tid >> 7;
        int node = isel[k*2 + sl];
        g_sel2[((b*NEe + k)*2 + sl)*128 + o] = sH[node*128 + o];
    }
}

__global__ void k_stats(const float* __restrict__ gamma, const float* __restrict__ beta) {
    int o = threadIdx.x;
    if (o < 128) {
        const double cnt = (double)(BRr * Nn);
        double m   = g_sum[o] / cnt;
        double var = g_sumsq[o] / cnt - m*m;
        double inv = 1.0 / sqrt(var + 1e-5);
        double a = inv * (double)gamma[o];
        g_a[o]  = a;
        g_c0[o] = (double)beta[o] - m * a;
    }
}

// ---------------- restructured flow kernels: 32 rows/CTA, smem-staged weights ----------------
// edge: smem = sg[32*384]d + wt[64*128]d + h[32*128]d + lg[32*4]d + P[32]i
__global__ __launch_bounds__(256) void k_edge_flow(
    const float* __restrict__ adj_deq, const float* __restrict__ eb1,
    const float* __restrict__ ew2, const float* __restrict__ eb2,
    float* __restrict__ out)
{
    extern __shared__ double dsm[];
    double* sg = dsm;              // 12288 doubles
    double* wt = dsm + 12288;      // 8192
    double* h  = dsm + 20480;      // 4096
    double* lg = dsm + 24576;      // 128
    int*    P  = (int*)(dsm + 24704);
    int tid = threadIdx.x;
    int row0 = blockIdx.x * 32;

    for (int idx = tid; idx < 32*384; idx += 256) {
        int rl = idx / 384, o = idx % 384;
        int row = row0 + rl;
        double v = 0.0;
        if (row < EROWS) {
            int b = row / NEe, k = row % NEe;
            if (o < 256) {
                int oo = o & 127;
                v = (double)g_sel2[(b*NEe + k)*256 + o] * g_a[oo] + g_c0[oo];
            } else {
                int oo = o - 256;
                v = (double)g_S[(b*Rr + Nn + k)*128 + oo] * g_a[oo] + 38.0 * g_c0[oo];
            }
        }
        sg[idx] = v;
    }
    if (tid < 32) P[tid] = 0;

    int wrp = tid >> 5, lane = tid & 31;
    int rbase = wrp * 4;
    for (int l = 0; l < Ll; l++) {
        double acc[4][4];
        #pragma unroll
        for (int q = 0; q < 4; q++) {
            double bq = (double)eb1[l*128 + lane*4 + q];
            acc[0][q] = bq; acc[1][q] = bq; acc[2][q] = bq; acc[3][q] = bq;
        }
        for (int tile = 0; tile < 6; tile++) {
            __syncthreads();
            const float* src = g_EW1T + l*49152 + tile*8192;
            for (int i = tid; i < 8192; i += 256) wt[i] = (double)src[i];
            __syncthreads();
            #pragma unroll 2
            for (int oo = 0; oo < 64; oo++) {
                double2 wA = *(const double2*)(wt + oo*128 + lane*4);
                double2 wB = *(const double2*)(wt + oo*128 + lane*4 + 2);
                #pragma unroll
                for (int r = 0; r < 4; r++) {
                    double s = sg[(rbase + r)*384 + tile*64 + oo];
                    acc[r][0] = fma(s, wA.x, acc[r][0]);
                    acc[r][1] = fma(s, wA.y, acc[r][1]);
                    acc[r][2] = fma(s, wB.x, acc[r][2]);
                    acc[r][3] = fma(s, wB.y, acc[r][3]);
                }
            }
        }
        #pragma unroll
        for (int r = 0; r < 4; r++)
            #pragma unroll
            for (int q = 0; q < 4; q++)
                h[(rbase + r)*128 + lane*4 + q] = tanh(acc[r][q]);
        __syncthreads();
        if (tid < 128) {
            int rl = tid >> 2, t = tid & 3;
            const float* W2 = ew2 + (l*4 + t)*128;
            double a = (double)eb2[l*4 + t];
            for (int c = 0; c < 128; c++) a = fma(h[rl*128 + c], (double)W2[c], a);
            lg[rl*4 + t] = a;
        }
        __syncthreads();
        if (tid < 32) {
            double best = lg[tid*4]; int bi = 0;
            if (lg[tid*4+1] > best) { best = lg[tid*4+1]; bi = 1; }
            if (lg[tid*4+2] > best) { best = lg[tid*4+2]; bi = 2; }
            if (lg[tid*4+3] > best) { best = lg[tid*4+3]; bi = 3; }
            P[tid] += bi;
        }
    }
    __syncthreads();
    if (tid < 128) {
        int rl = tid >> 2, j = tid & 3;
        int row = row0 + rl;
        if (row < EROWS) {
            int p = P[rl] & 3;
            out[NROWS*NTt + row*4 + j] = adj_deq[row*4 + ((j - p + 4) & 3)];
        }
    }
}

// node: smem = sg[32*128]d + wt[64*128]d + h[32*128]d + lg[32*9]d + P[32]i
__global__ __launch_bounds__(256) void k_node_flow(
    const float* __restrict__ x_deq, const float* __restrict__ nb1,
    const float* __restrict__ nw2, const float* __restrict__ nb2,
    float* __restrict__ out)
{
    extern __shared__ double dsm[];
    double* sg = dsm;              // 4096
    double* wt = dsm + 4096;       // 8192
    double* h  = dsm + 12288;      // 4096
    double* lg = dsm + 16384;      // 288
    int*    P  = (int*)(dsm + 16672);
    int tid = threadIdx.x;
    int row0 = blockIdx.x * 32;

    for (int idx = tid; idx < 32*128; idx += 256) {
        int rl = idx >> 7, o = idx & 127;
        int row = row0 + rl;
        int b = row / Nn, n = row % Nn;
        sg[idx] = (double)g_S[(b*Rr + n)*128 + o] * g_a[o] + 38.0 * g_c0[o];
    }
    if (tid < 32) P[tid] = 0;

    int wrp = tid >> 5, lane = tid & 31;
    int rbase = wrp * 4;
    for (int l = 0; l < Ll; l++) {
        double acc[4][4];
        #pragma unroll
        for (int q = 0; q < 4; q++) {
            double bq = (double)nb1[l*128 + lane*4 + q];
            acc[0][q] = bq; acc[1][q] = bq; acc[2][q] = bq; acc[3][q] = bq;
        }
        for (int tile = 0; tile < 2; tile++) {
            __syncthreads();
            const float* src = g_NW1T + l*16384 + tile*8192;
            for (int i = tid; i < 8192; i += 256) wt[i] = (double)src[i];
            __syncthreads();
            #pragma unroll 2
            for (int oo = 0; oo < 64; oo++) {
                double2 wA = *(const double2*)(wt + oo*128 + lane*4);
                double2 wB = *(const double2*)(wt + oo*128 + lane*4 + 2);
                #pragma unroll
                for (int r = 0; r < 4; r++) {
                    double s = sg[(rbase + r)*128 + tile*64 + oo];
                    acc[r][0] = fma(s, wA.x, acc[r][0]);
                    acc[r][1] = fma(s, wA.y, acc[r][1]);
                    acc[r][2] = fma(s, wB.x, acc[r][2]);
                    acc[r][3] = fma(s, wB.y, acc[r][3]);
                }
            }
        }
        #pragma unroll
        for (int r = 0; r < 4; r++)
            #pragma unroll
            for (int q = 0; q < 4; q++)
                h[(rbase + r)*128 + lane*4 + q] = tanh(acc[r][q]);
        __syncthreads();
        for (int pp = tid; pp < 32*NTt; pp += 256) {
            int rl = pp / NTt, t = pp % NTt;
            const float* W2 = nw2 + (l*NTt + t)*128;
            double a = (double)nb2[l*NTt + t];
            for (int c = 0; c < 128; c++) a = fma(h[rl*128 + c], (double)W2[c], a);
            lg[rl*NTt + t] = a;
        }
        __syncthreads();
        if (tid < 32) {
            double best = lg[tid*NTt]; int bi = 0;
            #pragma unroll
            for (int t = 1; t < NTt; t++) {
                double v = lg[tid*NTt + t];
                if (v > best) { best = v; bi = t; }
            }
            P[tid] += bi;
        }
    }
    __syncthreads();
    for (int pp = tid; pp < 32*NTt; pp += 256) {
        int rl = pp / NTt, j = pp % NTt;
        int row = row0 + rl;
        int p = P[rl] % NTt;
        out[row*NTt + j] = x_deq[row*NTt + ((j - p + 18) % NTt)];
    }
}

extern "C" void kernel_launch(void* const* d_in, const int* in_sizes, int n_in,
                              void* d_out, int out_size) {
    const float* x       = (const float*)d_in[0];
    const float* adj     = (const float*)d_in[1];
    const float* x_deq   = (const float*)d_in[2];
    const float* adj_deq = (const float*)d_in[3];
    const void*  mn      = d_in[4];
    const void*  me      = d_in[5];
    const int*   isel    = (const int*)d_in[6];
    const float* embw    = (const float*)d_in[7];
    const float* gc1     = (const float*)d_in[8];
    const float* gc2     = (const float*)d_in[9];
    const float* gc3     = (const float*)d_in[10];
    const float* gamma   = (const float*)d_in[11];
    const float* beta    = (const float*)d_in[12];
    const float* nw1     = (const float*)d_in[13];
    const float* nb1     = (const float*)d_in[14];
    const float* nw2     = (const float*)d_in[15];
    const float* nb2     = (const float*)d_in[16];
    const float* ew1     = (const float*)d_in[17];
    const float* eb1     = (const float*)d_in[18];
    const float* ew2     = (const float*)d_in[19];
    const float* eb2     = (const float*)d_in[20];
    float* out = (float*)d_out;

    cudaFuncSetAttribute(k_rgcn, cudaFuncAttributeMaxDynamicSharedMemorySize, 98304);
    cudaFuncSetAttribute(k_edge_flow, cudaFuncAttributeMaxDynamicSharedMemorySize, 199168);
    cudaFuncSetAttribute(k_node_flow, cudaFuncAttributeMaxDynamicSharedMemorySize, 135168);

    k_detect<<<1, 32>>>((const unsigned char*)mn);
    k_zero<<<1, 128>>>();
    k_prep_w<<<2304, 256>>>(gc2, gc3, ew1, nw1);
    k_prep_ps1<<<16, 384>>>(x, embw, gc1);
    k_rgcn<<<BRr, 256, 98048>>>(adj, mn, me, isel);
    k_stats<<<1, 128>>>(gamma, beta);
    k_node_flow<<<19, 256, 135168>>>(x_deq, nb1, nw2, nb2, out);
    k_edge_flow<<<352, 256, 199168>>>(adj_deq, eb1, ew2, eb2, out);
}

// round 5
// speedup vs baseline: 2.9276x; 2.0671x over previous
#include <cuda_runtime.h>
#include <math.h>

#define BB 16
#define Nn 38
#define NTt 9
#define NEe 703
#define Rr 741
#define BRr (BB*Rr)
#define Ll 12
#define EROWS (BB*NEe)   // 11248
#define NROWS (BB*Nn)    // 608
#define TAU 0.05f

typedef unsigned long long ull;

// ---------------- static device scratch ----------------
__device__ __align__(16) float  g_PS1[BB*Nn*384];
__device__ __align__(16) float  g_W2T[128*384];
__device__ __align__(16) float  g_W3T[128*384];
__device__ __align__(16) float  g_EW1T[Ll*384*128];  // [l][o][c]
__device__ __align__(16) float  g_NW1T[Ll*128*128];  // [l][o][c]
__device__ __align__(16) float  g_S[BRr*128];
__device__ __align__(16) double g_Sd[BRr*128];
__device__ __align__(16) float  g_sel2[BB*NEe*2*128];
__device__ double g_sum[128];
__device__ double g_sumsq[128];
__device__ double g_a[128];
__device__ double g_c0[128];
__device__ int    g_mode;

__device__ __forceinline__ bool read_mask(const void* p, int i, int mode) {
    if (mode == 0) return ((const unsigned char*)p)[i] != 0;
    if (mode == 1) return ((const float*)p)[i] != 0.0f;
    return ((const int*)p)[i] != 0;
}

// ---- packed f32x2 helpers (bit-identical rounding to scalar FFMA) ----
__device__ __forceinline__ ull pack2(float a, float b) {
    ull r; asm("mov.b64 %0, {%1, %2};" : "=l"(r) : "f"(a), "f"(b)); return r;
}
__device__ __forceinline__ void unpack2(ull v, float& x, float& y) {
    asm("mov.b64 {%0, %1}, %2;" : "=f"(x), "=f"(y) : "l"(v));
}
__device__ __forceinline__ void fma2(ull& d, ull a, ull b) {
    asm("fma.rn.f32x2 %0, %1, %2, %3;" : "=l"(d) : "l"(a), "l"(b), "l"(d));
}

__global__ void k_detect(const unsigned char* __restrict__ mn) {
    if (threadIdx.x == 0) {
        bool b8 = false, f32 = false;
        for (int i = 0; i < 152; i++) {
            unsigned char v = mn[i];
            if ((i & 3) != 0 && v == 1) b8 = true;
            if ((i & 3) == 3 && v == 0x3f) f32 = true;
        }
        g_mode = b8 ? 0 : (f32 ? 1 : 2);
    }
}

__global__ void k_zero() {
    int t = threadIdx.x;
    if (t < 128) { g_sum[t] = 0.0; g_sumsq[t] = 0.0; }
}

__global__ void k_prep_w(const float* __restrict__ gc2, const float* __restrict__ gc3,
                         const float* __restrict__ ew1, const float* __restrict__ nw1) {
    int i = blockIdx.x * 256 + threadIdx.x;
    if (i < 49152) {
        int k = i / 384, c = i % 384;
        g_W2T[i] = gc2[c*128 + k];
        g_W3T[i] = gc3[c*128 + k];
    }
    if (i < 589824) {
        int l = i / 49152, rem = i % 49152;
        int o = rem / 128, c = rem % 128;
        g_EW1T[i] = ew1[l*49152 + c*384 + o];
    }
    if (i < 196608) {
        int l = i / 16384, rem = i % 16384;
        int o = rem / 128, c = rem % 128;
        g_NW1T[i] = nw1[l*16384 + c*128 + o];
    }
}

__global__ void k_prep_ps1(const float* __restrict__ x, const float* __restrict__ embw,
                           const float* __restrict__ gc1) {
    __shared__ float h0[Nn*NTt];
    int b = blockIdx.x, t = threadIdx.x;
    if (t < Nn*NTt) {
        int j = t / NTt, tt = t % NTt;
        float acc = 0.f;
        #pragma unroll
        for (int u = 0; u < NTt; u++) acc += x[(b*Nn + j)*NTt + u] * embw[tt*NTt + u];
        h0[t] = acc;
    }
    __syncthreads();
    if (t < 384) {
        for (int j = 0; j < Nn; j++) {
            float acc = 0.f;
            #pragma unroll
            for (int u = 0; u < NTt; u++) acc += h0[j*NTt + u] * gc1[t*NTt + u];
            g_PS1[(b*Nn + j)*384 + t] = acc;
        }
    }
}

// ---------------- fused RGCN with f32x2 inner loops ----------------
__device__ __forceinline__ void block_einsum(const float* __restrict__ sA,
                                             const float* __restrict__ sS,
                                             float* __restrict__ sH,
                                             int tx, int ty, bool relu) {
    ull acc[5][2];
    #pragma unroll
    for (int ii = 0; ii < 5; ii++) { acc[ii][0] = 0ull; acc[ii][1] = 0ull; }
    #pragma unroll
    for (int e = 0; e < 3; e++) {
        const float* aE = sA + e*1600 + ty*40;
        const float* sE = sS + e*128 + tx*4;
        for (int j = 0; j < Nn; j++) {
            const ull* sp = (const ull*)(sE + j*384);
            ull s01 = sp[0], s23 = sp[1];
            #pragma unroll
            for (int ii = 0; ii < 5; ii++) {
                float a = aE[ii*320 + j];
                ull aa = pack2(a, a);
                fma2(acc[ii][0], aa, s01);
                fma2(acc[ii][1], aa, s23);
            }
        }
    }
    #pragma unroll
    for (int ii = 0; ii < 5; ii++) {
        int i = ty + 8*ii;
        float4 v;
        unpack2(acc[ii][0], v.x, v.y);
        unpack2(acc[ii][1], v.z, v.w);
        if (relu) {
            v.x = fmaxf(v.x, 0.f); v.y = fmaxf(v.y, 0.f);
            v.z = fmaxf(v.z, 0.f); v.w = fmaxf(v.w, 0.f);
        }
        *(float4*)(sH + i*128 + tx*4) = v;
    }
}

__device__ __forceinline__ void block_gemm(const float* __restrict__ WT,
                                           const float* __restrict__ sH,
                                           float* __restrict__ sS,
                                           int tx, int ty) {
    #pragma unroll 1
    for (int cc = 0; cc < 3; cc++) {
        ull acc[5][2];
        #pragma unroll
        for (int jj = 0; jj < 5; jj++) { acc[jj][0] = 0ull; acc[jj][1] = 0ull; }
        const float* wb = WT + cc*128 + tx*4;
        const float* hb = sH + ty*128;
        #pragma unroll 4
        for (int k = 0; k < 128; k++) {
            const ull* wp = (const ull*)(wb + k*384);
            ull w01 = wp[0], w23 = wp[1];
            #pragma unroll
            for (int jj = 0; jj < 5; jj++) {
                float h = hb[jj*1024 + k];
                ull hh = pack2(h, h);
                fma2(acc[jj][0], hh, w01);
                fma2(acc[jj][1], hh, w23);
            }
        }
        float* ob = sS + cc*128 + tx*4;
        #pragma unroll
        for (int jj = 0; jj < 5; jj++) {
            int j = ty + 8*jj;
            if (j < Nn) {
                ull* op = (ull*)(ob + j*384);
                op[0] = acc[jj][0];
                op[1] = acc[jj][1];
            }
        }
    }
}

__global__ __launch_bounds__(256) void k_rgcn(
    const float* __restrict__ adj, const void* __restrict__ maskn,
    const void* __restrict__ maske, const int* __restrict__ isel)
{
    extern __shared__ float sm[];
    float* sA = sm;            // 3*40*40
    float* sS = sm + 4800;     // 38*384
    float* sH = sm + 19392;    // 40*128
    int tid = threadIdx.x;
    int b = blockIdx.x / Rr, r = blockIdx.x % Rr;
    int mode = g_mode;

    for (int idx = tid; idx < 3*40*38; idx += 256) {
        int j = idx % 38;
        int i = (idx / 38) % 40;
        int e = idx / (38*40);
        float v = 0.f;
        if (i < Nn && read_mask(maske, r*1444 + i*38 + j, mode))
            v = adj[((b*4 + e)*38 + i)*38 + j];
        sA[e*1600 + i*40 + j] = v;
    }
    for (int idx = tid; idx < Nn*384; idx += 256) {
        int j = idx / 384;
        sS[idx] = read_mask(maskn, r*38 + j, mode) ? g_PS1[b*Nn*384 + idx] : 0.f;
    }
    __syncthreads();

    int tx = tid & 31, ty = tid >> 5;
    block_einsum(sA, sS, sH, tx, ty, true);   __syncthreads();
    block_gemm(g_W2T, sH, sS, tx, ty);        __syncthreads();
    block_einsum(sA, sS, sH, tx, ty, true);   __syncthreads();
    block_gemm(g_W3T, sH, sS, tx, ty);        __syncthreads();
    block_einsum(sA, sS, sH, tx, ty, false);  __syncthreads();

    if (tid < 128) {
        double s = 0.0, sq = 0.0;
        for (int i = 0; i < Nn; i++) {
            double v = (double)sH[i*128 + tid];
            s += v; sq += v*v;
        }
        g_S[blockIdx.x*128 + tid]  = (float)s;
        g_Sd[blockIdx.x*128 + tid] = s;
        atomicAdd(&g_sum[tid], s);
        atomicAdd(&g_sumsq[tid], sq);
    }
    if (r >= Nn) {
        int k = r - Nn;
        int o = tid & 127, sl = tid >> 7;
        int node = isel[k*2 + sl];
        g_sel2[((b*NEe + k)*2 + sl)*128 + o] = sH[node*128 + o];
    }
}

__global__ void k_stats(const float* __restrict__ gamma, const float* __restrict__ beta) {
    int o = threadIdx.x;
    if (o < 128) {
        const double cnt = (double)(BRr * Nn);
        double m   = g_sum[o] / cnt;
        double var = g_sumsq[o] / cnt - m*m;
        double inv = 1.0 / sqrt(var + 1e-5);
        double a = inv * (double)gamma[o];
        g_a[o]  = a;
        g_c0[o] = (double)beta[o] - m * a;
    }
}

// ---------------- flow kernels: fp32 fast path + fp64 fallback on small gaps ----------------
// edge smem floats: sg 12288 | wt 8192 | h 4096 | lg 128 | ints: bi 32, P 32, flags 32
__global__ __launch_bounds__(256) void k_edge_flow(
    const float* __restrict__ adj_deq, const float* __restrict__ eb1,
    const float* __restrict__ ew2, const float* __restrict__ eb2,
    float* __restrict__ out)
{
    extern __shared__ float fsm[];
    float* sg = fsm;               // 32*384
    float* wt = fsm + 12288;       // 64*128
    float* h  = fsm + 20480;       // 32*128
    float* lg = fsm + 24576;       // 32*4
    int* bi    = (int*)(fsm + 24704);
    int* P     = bi + 32;
    int* flags = bi + 64;
    int tid = threadIdx.x;
    int row0 = blockIdx.x * 32;

    for (int idx = tid; idx < 32*384; idx += 256) {
        int rl = idx / 384, o = idx % 384;
        int row = row0 + rl;
        double v = 0.0;
        if (row < EROWS) {
            int b = row / NEe, k = row % NEe;
            if (o < 256) {
                int oo = o & 127;
                v = (double)g_sel2[(b*NEe + k)*256 + o] * g_a[oo] + g_c0[oo];
            } else {
                int oo = o - 256;
                v = g_Sd[(b*Rr + Nn + k)*128 + oo] * g_a[oo] + 38.0 * g_c0[oo];
            }
        }
        sg[idx] = (float)v;
    }
    if (tid < 32) P[tid] = 0;

    int wrp = tid >> 5, lane = tid & 31;
    int rbase = wrp * 4;
    for (int l = 0; l < Ll; l++) {
        float acc[4][4];
        #pragma unroll
        for (int q = 0; q < 4; q++) {
            float bq = eb1[l*128 + lane*4 + q];
            acc[0][q] = bq; acc[1][q] = bq; acc[2][q] = bq; acc[3][q] = bq;
        }
        for (int tile = 0; tile < 6; tile++) {
            __syncthreads();
            const float* src = g_EW1T + l*49152 + tile*8192;
            for (int i = tid; i < 8192; i += 256) wt[i] = src[i];
            __syncthreads();
            #pragma unroll 2
            for (int oo = 0; oo < 64; oo++) {
                float4 w4 = *(const float4*)(wt + oo*128 + lane*4);
                #pragma unroll
                for (int r = 0; r < 4; r++) {
                    float s = sg[(rbase + r)*384 + tile*64 + oo];
                    acc[r][0] = fmaf(s, w4.x, acc[r][0]);
                    acc[r][1] = fmaf(s, w4.y, acc[r][1]);
                    acc[r][2] = fmaf(s, w4.z, acc[r][2]);
                    acc[r][3] = fmaf(s, w4.w, acc[r][3]);
                }
            }
        }
        #pragma unroll
        for (int r = 0; r < 4; r++)
            #pragma unroll
            for (int q = 0; q < 4; q++)
                h[(rbase + r)*128 + lane*4 + q] = tanhf(acc[r][q]);
        __syncthreads();
        if (tid < 128) {
            int rl = tid >> 2, t = tid & 3;
            const float* W2 = ew2 + (l*4 + t)*128;
            float a = eb2[l*4 + t];
            for (int c = 0; c < 128; c++) a = fmaf(h[rl*128 + c], W2[c], a);
            lg[rl*4 + t] = a;
        }
        __syncthreads();
        if (tid < 32) {
            float l0 = lg[tid*4], l1 = lg[tid*4+1], l2 = lg[tid*4+2], l3 = lg[tid*4+3];
            float best = l0; int bx = 0;
            if (l1 > best) { best = l1; bx = 1; }
            if (l2 > best) { best = l2; bx = 2; }
            if (l3 > best) { best = l3; bx = 3; }
            float second = -1e30f;
            if (bx != 0 && l0 > second) second = l0;
            if (bx != 1 && l1 > second) second = l1;
            if (bx != 2 && l2 > second) second = l2;
            if (bx != 3 && l3 > second) second = l3;
            bi[tid] = bx;
            flags[tid] = (best - second < TAU) && (row0 + tid < EROWS);
        }
        __syncthreads();
        // fp64 recompute for flagged rows (warp-collective, rare)
        for (int r = 0; r < 4; r++) {
            int rl = rbase + r;
            if (!flags[rl]) continue;
            int row = row0 + rl;
            int b = row / NEe, k = row % NEe;
            const float* W1 = g_EW1T + l*49152;
            double accd[4];
            #pragma unroll
            for (int q = 0; q < 4; q++) accd[q] = (double)eb1[l*128 + lane + 32*q];
            for (int o = 0; o < 384; o++) {
                double gv;
                if (o < 256) {
                    int oo = o & 127;
                    gv = (double)g_sel2[(b*NEe + k)*256 + o] * g_a[oo] + g_c0[oo];
                } else {
                    int oo = o - 256;
                    gv = g_Sd[(b*Rr + Nn + k)*128 + oo] * g_a[oo] + 38.0 * g_c0[oo];
                }
                #pragma unroll
                for (int q = 0; q < 4; q++)
                    accd[q] = fma(gv, (double)W1[o*128 + lane + 32*q], accd[q]);
            }
            double hd[4];
            #pragma unroll
            for (int q = 0; q < 4; q++) hd[q] = tanh(accd[q]);
            double lgd[4];
            #pragma unroll
            for (int t = 0; t < 4; t++) {
                const float* W2 = ew2 + (l*4 + t)*128;
                double p = 0.0;
                #pragma unroll
                for (int q = 0; q < 4; q++) p = fma(hd[q], (double)W2[lane + 32*q], p);
                #pragma unroll
                for (int s = 16; s > 0; s >>= 1) p += __shfl_down_sync(0xffffffffu, p, s);
                lgd[t] = p;
            }
            if (lane == 0) {
                #pragma unroll
                for (int t = 0; t < 4; t++) lgd[t] += (double)eb2[l*4 + t];
                double best = lgd[0]; int bx = 0;
                if (lgd[1] > best) { best = lgd[1]; bx = 1; }
                if (lgd[2] > best) { best = lgd[2]; bx = 2; }
                if (lgd[3] > best) { best = lgd[3]; bx = 3; }
                bi[rl] = bx;
            }
        }
        __syncthreads();
        if (tid < 32) P[tid] += bi[tid];
    }
    __syncthreads();
    if (tid < 128) {
        int rl = tid >> 2, j = tid & 3;
        int row = row0 + rl;
        if (row < EROWS) {
            int p = P[rl] & 3;
            out[NROWS*NTt + row*4 + j] = adj_deq[row*4 + ((j - p + 4) & 3)];
        }
    }
}

// node smem floats: sg 4096 | wt 8192 | h 4096 | lg 288 | ints: bi 32, P 32, flags 32
__global__ __launch_bounds__(256) void k_node_flow(
    const float* __restrict__ x_deq, const float* __restrict__ nb1,
    const float* __restrict__ nw2, const float* __restrict__ nb2,
    float* __restrict__ out)
{
    extern __shared__ float fsm[];
    float* sg = fsm;               // 32*128
    float* wt = fsm + 4096;        // 64*128
    float* h  = fsm + 12288;       // 32*128
    float* lg = fsm + 16384;       // 32*9
    int* bi    = (int*)(fsm + 16672);
    int* P     = bi + 32;
    int* flags = bi + 64;
    int tid = threadIdx.x;
    int row0 = blockIdx.x * 32;

    for (int idx = tid; idx < 32*128; idx += 256) {
        int rl = idx >> 7, o = idx & 127;
        int row = row0 + rl;
        int b = row / Nn, n = row % Nn;
        sg[idx] = (float)(g_Sd[(b*Rr + n)*128 + o] * g_a[o] + 38.0 * g_c0[o]);
    }
    if (tid < 32) P[tid] = 0;

    int wrp = tid >> 5, lane = tid & 31;
    int rbase = wrp * 4;
    for (int l = 0; l < Ll; l++) {
        float acc[4][4];
        #pragma unroll
        for (int q = 0; q < 4; q++) {
            float bq = nb1[l*128 + lane*4 + q];
            acc[0][q] = bq; acc[1][q] = bq; acc[2][q] = bq; acc[3][q] = bq;
        }
        for (int tile = 0; tile < 2; tile++) {
            __syncthreads();
            const float* src = g_NW1T + l*16384 + tile*8192;
            for (int i = tid; i < 8192; i += 256) wt[i] = src[i];
            __syncthreads();
            #pragma unroll 2
            for (int oo = 0; oo < 64; oo++) {
                float4 w4 = *(const float4*)(wt + oo*128 + lane*4);
                #pragma unroll
                for (int r = 0; r < 4; r++) {
                    float s = sg[(rbase + r)*128 + tile*64 + oo];
                    acc[r][0] = fmaf(s, w4.x, acc[r][0]);
                    acc[r][1] = fmaf(s, w4.y, acc[r][1]);
                    acc[r][2] = fmaf(s, w4.z, acc[r][2]);
                    acc[r][3] = fmaf(s, w4.w, acc[r][3]);
                }
            }
        }
        #pragma unroll
        for (int r = 0; r < 4; r++)
            #pragma unroll
            for (int q = 0; q < 4; q++)
                h[(rbase + r)*128 + lane*4 + q] = tanhf(acc[r][q]);
        __syncthreads();
        for (int pp = tid; pp < 32*NTt; pp += 256) {
            int rl = pp / NTt, t = pp % NTt;
            const float* W2 = nw2 + (l*NTt + t)*128;
            float a = nb2[l*NTt + t];
            for (int c = 0; c < 128; c++) a = fmaf(h[rl*128 + c], W2[c], a);
            lg[rl*NTt + t] = a;
        }
        __syncthreads();
        if (tid < 32) {
            float best = lg[tid*NTt]; int bx = 0;
            #pragma unroll
            for (int t = 1; t < NTt; t++) {
                float v = lg[tid*NTt + t];
                if (v > best) { best = v; bx = t; }
            }
            float second = -1e30f;
            #pragma unroll
            for (int t = 0; t < NTt; t++) {
                float v = lg[tid*NTt + t];
                if (t != bx && v > second) second = v;
            }
            bi[tid] = bx;
            flags[tid] = (best - second < TAU);
        }
        __syncthreads();
        for (int r = 0; r < 4; r++) {
            int rl = rbase + r;
            if (!flags[rl]) continue;
            int row = row0 + rl;
            int b = row / Nn, n = row % Nn;
            const float* W1 = g_NW1T + l*16384;
            double accd[4];
            #pragma unroll
            for (int q = 0; q < 4; q++) accd[q] = (double)nb1[l*128 + lane + 32*q];
            for (int o = 0; o < 128; o++) {
                double gv = g_Sd[(b*Rr + n)*128 + o] * g_a[o] + 38.0 * g_c0[o];
                #pragma unroll
                for (int q = 0; q < 4; q++)
                    accd[q] = fma(gv, (double)W1[o*128 + lane + 32*q], accd[q]);
            }
            double hd[4];
            #pragma unroll
            for (int q = 0; q < 4; q++) hd[q] = tanh(accd[q]);
            double best = -1e300; int bx = 0;
            for (int t = 0; t < NTt; t++) {
                const float* W2 = nw2 + (l*NTt + t)*128;
                double p = 0.0;
                #pragma unroll
                for (int q = 0; q < 4; q++) p = fma(hd[q], (double)W2[lane + 32*q], p);
                #pragma unroll
                for (int s = 16; s > 0; s >>= 1) p += __shfl_down_sync(0xffffffffu, p, s);
                if (lane == 0) {
                    p += (double)nb2[l*NTt + t];
                    if (p > best) { best = p; bx = t; }
                }
            }
            if (lane == 0) bi[rl] = bx;
        }
        __syncthreads();
        if (tid < 32) P[tid] += bi[tid];
    }
    __syncthreads();
    for (int pp = tid; pp < 32*NTt; pp += 256) {
        int rl = pp / NTt, j = pp % NTt;
        int row = row0 + rl;
        int p = P[rl] % NTt;
        out[row*NTt + j] = x_deq[row*NTt + ((j - p + 18) % NTt)];
    }
}

extern "C" void kernel_launch(void* const* d_in, const int* in_sizes, int n_in,
                              void* d_out, int out_size) {
    const float* x       = (const float*)d_in[0];
    const float* adj     = (const float*)d_in[1];
    const float* x_deq   = (const float*)d_in[2];
    const float* adj_deq = (const float*)d_in[3];
    const void*  mn      = d_in[4];
    const void*  me      = d_in[5];
    const int*   isel    = (const int*)d_in[6];
    const float* embw    = (const float*)d_in[7];
    const float* gc1     = (const float*)d_in[8];
    const float* gc2     = (const float*)d_in[9];
    const float* gc3     = (const float*)d_in[10];
    const float* gamma   = (const float*)d_in[11];
    const float* beta    = (const float*)d_in[12];
    const float* nw1     = (const float*)d_in[13];
    const float* nb1     = (const float*)d_in[14];
    const float* nw2     = (const float*)d_in[15];
    const float* nb2     = (const float*)d_in[16];
    const float* ew1     = (const float*)d_in[17];
    const float* eb1     = (const float*)d_in[18];
    const float* ew2     = (const float*)d_in[19];
    const float* eb2     = (const float*)d_in[20];
    float* out = (float*)d_out;

    cudaFuncSetAttribute(k_rgcn, cudaFuncAttributeMaxDynamicSharedMemorySize, 98304);
    cudaFuncSetAttribute(k_edge_flow, cudaFuncAttributeMaxDynamicSharedMemorySize, 99200);
    cudaFuncSetAttribute(k_node_flow, cudaFuncAttributeMaxDynamicSharedMemorySize, 67072);

    k_detect<<<1, 32>>>((const unsigned char*)mn);
    k_zero<<<1, 128>>>();
    k_prep_w<<<2304, 256>>>(gc2, gc3, ew1, nw1);
    k_prep_ps1<<<16, 384>>>(x, embw, gc1);
    k_rgcn<<<BRr, 256, 98048>>>(adj, mn, me, isel);
    k_stats<<<1, 128>>>(gamma, beta);
    k_node_flow<<<19, 256, 67072>>>(x_deq, nb1, nw2, nb2, out);
    k_edge_flow<<<352, 256, 99200>>>(adj_deq, eb1, ew2, eb2, out);
}

// round 6
// speedup vs baseline: 4.5397x; 1.5507x over previous
#include <cuda_runtime.h>
#include <math.h>

#define BB 16
#define Nn 38
#define NTt 9
#define NEe 703
#define Rr 741
#define BRr (BB*Rr)
#define Ll 12
#define EROWS (BB*NEe)   // 11248
#define NROWS (BB*Nn)    // 608
#define TAU 0.015f

typedef unsigned long long ull;

// ---------------- static device scratch ----------------
__device__ __align__(16) float  g_PS1[BB*Nn*384];
__device__ __align__(16) float  g_W2T[128*384];
__device__ __align__(16) float  g_W3T[128*384];
__device__ __align__(16) float  g_EW1T[Ll*384*128];  // [l][o][c]
__device__ __align__(16) float  g_NW1T[Ll*128*128];  // [l][o][c]
__device__ __align__(16) double g_Sd[BRr*128];
__device__ __align__(16) float  g_sel2[BB*NEe*2*128];
__device__ double g_sum[128];
__device__ double g_sumsq[128];
__device__ double g_a[128];
__device__ double g_c0[128];
__device__ int    g_mode;

__device__ __forceinline__ bool read_mask(const void* p, int i, int mode) {
    if (mode == 0) return ((const unsigned char*)p)[i] != 0;
    if (mode == 1) return ((const float*)p)[i] != 0.0f;
    return ((const int*)p)[i] != 0;
}

// ---- packed f32x2 helpers (lane-wise rounding identical to scalar FFMA) ----
__device__ __forceinline__ ull pack2(float a, float b) {
    ull r; asm("mov.b64 %0, {%1, %2};" : "=l"(r) : "f"(a), "f"(b)); return r;
}
__device__ __forceinline__ void unpack2(ull v, float& x, float& y) {
    asm("mov.b64 {%0, %1}, %2;" : "=f"(x), "=f"(y) : "l"(v));
}
__device__ __forceinline__ void fma2(ull& d, ull a, ull b) {
    asm("fma.rn.f32x2 %0, %1, %2, %3;" : "=l"(d) : "l"(a), "l"(b), "l"(d));
}
__device__ __forceinline__ float f4c(const float4& v, int i) {
    return i == 0 ? v.x : (i == 1 ? v.y : (i == 2 ? v.z : v.w));
}

// init: mask-dtype detect + stat zero (merged so k_rgcn lands in ncu slot 3)
__global__ void k_init(const unsigned char* __restrict__ mn) {
    int t = threadIdx.x;
    if (t < 128) { g_sum[t] = 0.0; g_sumsq[t] = 0.0; }
    if (t == 0) {
        bool b8 = false, f32 = false;
        for (int i = 0; i < 152; i++) {
            unsigned char v = mn[i];
            if ((i & 3) != 0 && v == 1) b8 = true;
            if ((i & 3) == 3 && v == 0x3f) f32 = true;
        }
        g_mode = b8 ? 0 : (f32 ? 1 : 2);
    }
}

__global__ void k_prep_w(const float* __restrict__ gc2, const float* __restrict__ gc3,
                         const float* __restrict__ ew1, const float* __restrict__ nw1) {
    int i = blockIdx.x * 256 + threadIdx.x;
    if (i < 49152) {
        int k = i / 384, c = i % 384;
        g_W2T[i] = gc2[c*128 + k];
        g_W3T[i] = gc3[c*128 + k];
    }
    if (i < 589824) {
        int l = i / 49152, rem = i % 49152;
        int o = rem / 128, c = rem % 128;
        g_EW1T[i] = ew1[l*49152 + c*384 + o];
    }
    if (i < 196608) {
        int l = i / 16384, rem = i % 16384;
        int o = rem / 128, c = rem % 128;
        g_NW1T[i] = nw1[l*16384 + c*128 + o];
    }
}

__global__ void k_prep_ps1(const float* __restrict__ x, const float* __restrict__ embw,
                           const float* __restrict__ gc1) {
    __shared__ float h0[Nn*NTt];
    int b = blockIdx.x, t = threadIdx.x;
    if (t < Nn*NTt) {
        int j = t / NTt, tt = t % NTt;
        float acc = 0.f;
        #pragma unroll
        for (int u = 0; u < NTt; u++) acc += x[(b*Nn + j)*NTt + u] * embw[tt*NTt + u];
        h0[t] = acc;
    }
    __syncthreads();
    if (t < 384) {
        for (int j = 0; j < Nn; j++) {
            float acc = 0.f;
            #pragma unroll
            for (int u = 0; u < NTt; u++) acc += h0[j*NTt + u] * gc1[t*NTt + u];
            g_PS1[(b*Nn + j)*384 + t] = acc;
        }
    }
}

// ---------------- fused RGCN: f32x2 math, LDS.128-only smem traffic ----------------
// out[i][o] = sum_{e,j} sA[e][i][j] * sS[j][e*128+o]   (sS padded to 40 rows, sA 3x40x40)
__device__ __forceinline__ void block_einsum(const float* __restrict__ sA,
                                             const float* __restrict__ sS,
                                             float* __restrict__ sH,
                                             int tx, int ty, bool relu) {
    ull acc[5][2];
    #pragma unroll
    for (int ii = 0; ii < 5; ii++) { acc[ii][0] = 0ull; acc[ii][1] = 0ull; }
    #pragma unroll
    for (int e = 0; e < 3; e++) {
        const float* aE = sA + e*1600 + ty*40;
        const float* sE = sS + e*128 + tx*4;
        #pragma unroll 2
        for (int j = 0; j < 40; j += 4) {
            float4 a4[5];
            #pragma unroll
            for (int ii = 0; ii < 5; ii++) a4[ii] = *(const float4*)(aE + ii*320 + j);
            #pragma unroll
            for (int dj = 0; dj < 4; dj++) {
                ulonglong2 s2 = *(const ulonglong2*)(sE + (j + dj)*384);
                #pragma unroll
                for (int ii = 0; ii < 5; ii++) {
                    float av = f4c(a4[ii], dj);
                    ull aa = pack2(av, av);
                    fma2(acc[ii][0], aa, s2.x);
                    fma2(acc[ii][1], aa, s2.y);
                }
            }
        }
    }
    #pragma unroll
    for (int ii = 0; ii < 5; ii++) {
        int i = ty + 8*ii;
        float4 v;
        unpack2(acc[ii][0], v.x, v.y);
        unpack2(acc[ii][1], v.z, v.w);
        if (relu) {
            v.x = fmaxf(v.x, 0.f); v.y = fmaxf(v.y, 0.f);
            v.z = fmaxf(v.z, 0.f); v.w = fmaxf(v.w, 0.f);
        }
        *(float4*)(sH + i*128 + tx*4) = v;
    }
}

// sS[j][c] = sum_k sH[j][k] * WT[k][c]
__device__ __forceinline__ void block_gemm(const float* __restrict__ WT,
                                           const float* __restrict__ sH,
                                           float* __restrict__ sS,
                                           int tx, int ty) {
    #pragma unroll 1
    for (int cc = 0; cc < 3; cc++) {
        ull acc[5][2];
        #pragma unroll
        for (int jj = 0; jj < 5; jj++) { acc[jj][0] = 0ull; acc[jj][1] = 0ull; }
        const float* wb = WT + cc*128 + tx*4;
        const float* hb = sH + ty*128;
        #pragma unroll 2
        for (int k = 0; k < 128; k += 4) {
            float4 h4[5];
            #pragma unroll
            for (int jj = 0; jj < 5; jj++) h4[jj] = *(const float4*)(hb + jj*1024 + k);
            #pragma unroll
            for (int dk = 0; dk < 4; dk++) {
                ulonglong2 w2 = *(const ulonglong2*)(wb + (k + dk)*384);
                #pragma unroll
                for (int jj = 0; jj < 5; jj++) {
                    float hv = f4c(h4[jj], dk);
                    ull hh = pack2(hv, hv);
                    fma2(acc[jj][0], hh, w2.x);
                    fma2(acc[jj][1], hh, w2.y);
                }
            }
        }
        float* ob = sS + cc*128 + tx*4;
        #pragma unroll
        for (int jj = 0; jj < 5; jj++) {
            int j = ty + 8*jj;
            if (j < Nn) {
                ull* op = (ull*)(ob + j*384);
                op[0] = acc[jj][0];
                op[1] = acc[jj][1];
            }
        }
    }
}

__global__ __launch_bounds__(256) void k_rgcn(
    const float* __restrict__ adj, const void* __restrict__ maskn,
    const void* __restrict__ maske, const int* __restrict__ isel)
{
    extern __shared__ float sm[];
    float* sA = sm;            // 3*40*40 = 4800
    float* sS = sm + 4800;     // 40*384 = 15360 (rows 38,39 zero)
    float* sH = sm + 20160;    // 40*128 = 5120
    int tid = threadIdx.x;
    int b = blockIdx.x / Rr, r = blockIdx.x % Rr;
    int mode = g_mode;

    for (int idx = tid; idx < 3*40*40; idx += 256) {
        int j = idx % 40;
        int i = (idx / 40) % 40;
        int e = idx / 1600;
        float v = 0.f;
        if (i < Nn && j < Nn && read_mask(maske, r*1444 + i*38 + j, mode))
            v = adj[((b*4 + e)*38 + i)*38 + j];
        sA[idx] = v;
    }
    for (int idx = tid; idx < 40*384; idx += 256) {
        int j = idx / 384, c = idx % 384;
        float v = 0.f;
        if (j < Nn && read_mask(maskn, r*38 + j, mode))
            v = g_PS1[(b*Nn + j)*384 + c];
        sS[idx] = v;
    }
    __syncthreads();

    int tx = tid & 31, ty = tid >> 5;
    block_einsum(sA, sS, sH, tx, ty, true);   __syncthreads();
    block_gemm(g_W2T, sH, sS, tx, ty);        __syncthreads();
    block_einsum(sA, sS, sH, tx, ty, true);   __syncthreads();
    block_gemm(g_W3T, sH, sS, tx, ty);        __syncthreads();
    block_einsum(sA, sS, sH, tx, ty, false);  __syncthreads();

    if (tid < 128) {
        double s = 0.0, sq = 0.0;
        for (int i = 0; i < Nn; i++) {
            double v = (double)sH[i*128 + tid];
            s += v; sq += v*v;
        }
        g_Sd[blockIdx.x*128 + tid] = s;
        atomicAdd(&g_sum[tid], s);
        atomicAdd(&g_sumsq[tid], sq);
    }
    if (r >= Nn) {
        int k = r - Nn;
        int o = tid & 127, sl = tid >> 7;
        int node = isel[k*2 + sl];
        g_sel2[((b*NEe + k)*2 + sl)*128 + o] = sH[node*128 + o];
    }
}

__global__ void k_stats(const float* __restrict__ gamma, const float* __restrict__ beta) {
    int o = threadIdx.x;
    if (o < 128) {
        const double cnt = (double)(BRr * Nn);
        double m   = g_sum[o] / cnt;
        double var = g_sumsq[o] / cnt - m*m;
        double inv = 1.0 / sqrt(var + 1e-5);
        double a = inv * (double)gamma[o];
        g_a[o]  = a;
        g_c0[o] = (double)beta[o] - m * a;
    }
}

// ---------------- flow kernels: fp32 fast path + fp64 fallback on small gaps ----------------
__global__ __launch_bounds__(256) void k_edge_flow(
    const float* __restrict__ adj_deq, const float* __restrict__ eb1,
    const float* __restrict__ ew2, const float* __restrict__ eb2,
    float* __restrict__ out)
{
    extern __shared__ float fsm[];
    float* sg = fsm;               // 32*384
    float* wt = fsm + 12288;       // 64*128
    float* h  = fsm + 20480;       // 32*128
    float* lg = fsm + 24576;       // 32*4
    int* bi    = (int*)(fsm + 24704);
    int* P     = bi + 32;
    int* flags = bi + 64;
    int tid = threadIdx.x;
    int row0 = blockIdx.x * 32;

    for (int idx = tid; idx < 32*384; idx += 256) {
        int rl = idx / 384, o = idx % 384;
        int row = row0 + rl;
        double v = 0.0;
        if (row < EROWS) {
            int b = row / NEe, k = row % NEe;
            if (o < 256) {
                int oo = o & 127;
                v = (double)g_sel2[(b*NEe + k)*256 + o] * g_a[oo] + g_c0[oo];
            } else {
                int oo = o - 256;
                v = g_Sd[(b*Rr + Nn + k)*128 + oo] * g_a[oo] + 38.0 * g_c0[oo];
            }
        }
        sg[idx] = (float)v;
    }
    if (tid < 32) P[tid] = 0;

    int wrp = tid >> 5, lane = tid & 31;
    int rbase = wrp * 4;
    for (int l = 0; l < Ll; l++) {
        ull acc[4][2];
        {
            float b0 = eb1[l*128 + lane*4+0], b1 = eb1[l*128 + lane*4+1];
            float b2 = eb1[l*128 + lane*4+2], b3 = eb1[l*128 + lane*4+3];
            ull p01 = pack2(b0, b1), p23 = pack2(b2, b3);
            #pragma unroll
            for (int r = 0; r < 4; r++) { acc[r][0] = p01; acc[r][1] = p23; }
        }
        for (int tile = 0; tile < 6; tile++) {
            __syncthreads();
            const float* src = g_EW1T + l*49152 + tile*8192;
            for (int i = tid*4; i < 8192; i += 1024)
                *(float4*)(wt + i) = *(const float4*)(src + i);
            __syncthreads();
            #pragma unroll 2
            for (int oo = 0; oo < 64; oo += 4) {
                float4 s4[4];
                #pragma unroll
                for (int r = 0; r < 4; r++)
                    s4[r] = *(const float4*)(sg + (rbase + r)*384 + tile*64 + oo);
                #pragma unroll
                for (int doo = 0; doo < 4; doo++) {
                    ulonglong2 w2 = *(const ulonglong2*)(wt + (oo + doo)*128 + lane*4);
                    #pragma unroll
                    for (int r = 0; r < 4; r++) {
                        float sv = f4c(s4[r], doo);
                        ull ss = pack2(sv, sv);
                        fma2(acc[r][0], ss, w2.x);
                        fma2(acc[r][1], ss, w2.y);
                    }
                }
            }
        }
        #pragma unroll
        for (int r = 0; r < 4; r++) {
            float a0, a1, a2, a3;
            unpack2(acc[r][0], a0, a1);
            unpack2(acc[r][1], a2, a3);
            float* hp = h + (rbase + r)*128 + lane*4;
            hp[0] = tanhf(a0); hp[1] = tanhf(a1); hp[2] = tanhf(a2); hp[3] = tanhf(a3);
        }
        __syncthreads();
        if (tid < 128) {
            int rl = tid >> 2, t = tid & 3;
            const float* W2 = ew2 + (l*4 + t)*128;
            float a = eb2[l*4 + t];
            for (int c = 0; c < 128; c++) a = fmaf(h[rl*128 + c], W2[c], a);
            lg[rl*4 + t] = a;
        }
        __syncthreads();
        if (tid < 32) {
            float l0 = lg[tid*4], l1 = lg[tid*4+1], l2 = lg[tid*4+2], l3 = lg[tid*4+3];
            float best = l0; int bx = 0;
            if (l1 > best) { best = l1; bx = 1; }
            if (l2 > best) { best = l2; bx = 2; }
            if (l3 > best) { best = l3; bx = 3; }
            float second = -1e30f;
            if (bx != 0 && l0 > second) second = l0;
            if (bx != 1 && l1 > second) second = l1;
            if (bx != 2 && l2 > second) second = l2;
            if (bx != 3 && l3 > second) second = l3;
            bi[tid] = bx;
            flags[tid] = (best - second < TAU) && (row0 + tid < EROWS);
        }
        __syncthreads();
        for (int r = 0; r < 4; r++) {
            int rl = rbase + r;
            if (!flags[rl]) continue;
            int row = row0 + rl;
            int b = row / NEe, k = row % NEe;
            const float* W1 = g_EW1T + l*49152;
            double accd[4];
            #pragma unroll
            for (int q = 0; q < 4; q++) accd[q] = (double)eb1[l*128 + lane + 32*q];
            for (int o = 0; o < 384; o++) {
                double gv;
                if (o < 256) {
                    int oo = o & 127;
                    gv = (double)g_sel2[(b*NEe + k)*256 + o] * g_a[oo] + g_c0[oo];
                } else {
                    int oo = o - 256;
                    gv = g_Sd[(b*Rr + Nn + k)*128 + oo] * g_a[oo] + 38.0 * g_c0[oo];
                }
                #pragma unroll
                for (int q = 0; q < 4; q++)
                    accd[q] = fma(gv, (double)W1[o*128 + lane + 32*q], accd[q]);
            }
            double hd[4];
            #pragma unroll
            for (int q = 0; q < 4; q++) hd[q] = tanh(accd[q]);
            double lgd[4];
            #pragma unroll
            for (int t = 0; t < 4; t++) {
                const float* W2 = ew2 + (l*4 + t)*128;
                double p = 0.0;
                #pragma unroll
                for (int q = 0; q < 4; q++) p = fma(hd[q], (double)W2[lane + 32*q], p);
                #pragma unroll
                for (int s = 16; s > 0; s >>= 1) p += __shfl_down_sync(0xffffffffu, p, s);
                lgd[t] = p;
            }
            if (lane == 0) {
                #pragma unroll
                for (int t = 0; t < 4; t++) lgd[t] += (double)eb2[l*4 + t];
                double best = lgd[0]; int bx = 0;
                if (lgd[1] > best) { best = lgd[1]; bx = 1; }
                if (lgd[2] > best) { best = lgd[2]; bx = 2; }
                if (lgd[3] > best) { best = lgd[3]; bx = 3; }
                bi[rl] = bx;
            }
        }
        __syncthreads();
        if (tid < 32) P[tid] += bi[tid];
    }
    __syncthreads();
    if (tid < 128) {
        int rl = tid >> 2, j = tid & 3;
        int row = row0 + rl;
        if (row < EROWS) {
            int p = P[rl] & 3;
            out[NROWS*NTt + row*4 + j] = adj_deq[row*4 + ((j - p + 4) & 3)];
        }
    }
}

__global__ __launch_bounds__(256) void k_node_flow(
    const float* __restrict__ x_deq, const float* __restrict__ nb1,
    const float* __restrict__ nw2, const float* __restrict__ nb2,
    float* __restrict__ out)
{
    extern __shared__ float fsm[];
    float* sg = fsm;               // 32*128
    float* wt = fsm + 4096;        // 64*128
    float* h  = fsm + 12288;       // 32*128
    float* lg = fsm + 16384;       // 32*9
    int* bi    = (int*)(fsm + 16672);
    int* P     = bi + 32;
    int* flags = bi + 64;
    int tid = threadIdx.x;
    int row0 = blockIdx.x * 32;

    for (int idx = tid; idx < 32*128; idx += 256) {
        int rl = idx >> 7, o = idx & 127;
        int row = row0 + rl;
        int b = row / Nn, n = row % Nn;
        sg[idx] = (float)(g_Sd[(b*Rr + n)*128 + o] * g_a[o] + 38.0 * g_c0[o]);
    }
    if (tid < 32) P[tid] = 0;

    int wrp = tid >> 5, lane = tid & 31;
    int rbase = wrp * 4;
    for (int l = 0; l < Ll; l++) {
        float acc[4][4];
        #pragma unroll
        for (int q = 0; q < 4; q++) {
            float bq = nb1[l*128 + lane*4 + q];
            acc[0][q] = bq; acc[1][q] = bq; acc[2][q] = bq; acc[3][q] = bq;
        }
        for (int tile = 0; tile < 2; tile++) {
            __syncthreads();
            const float* src = g_NW1T + l*16384 + tile*8192;
            for (int i = tid*4; i < 8192; i += 1024)
                *(float4*)(wt + i) = *(const float4*)(src + i);
            __syncthreads();
            #pragma unroll 2
            for (int oo = 0; oo < 64; oo++) {
                float4 w4 = *(const float4*)(wt + oo*128 + lane*4);
                #pragma unroll
                for (int r = 0; r < 4; r++) {
                    float s = sg[(rbase + r)*128 + tile*64 + oo];
                    acc[r][0] = fmaf(s, w4.x, acc[r][0]);
                    acc[r][1] = fmaf(s, w4.y, acc[r][1]);
                    acc[r][2] = fmaf(s, w4.z, acc[r][2]);
                    acc[r][3] = fmaf(s, w4.w, acc[r][3]);
                }
            }
        }
        #pragma unroll
        for (int r = 0; r < 4; r++)
            #pragma unroll
            for (int q = 0; q < 4; q++)
                h[(rbase + r)*128 + lane*4 + q] = tanhf(acc[r][q]);
        __syncthreads();
        for (int pp = tid; pp < 32*NTt; pp += 256) {
            int rl = pp / NTt, t = pp % NTt;
            const float* W2 = nw2 + (l*NTt + t)*128;
            float a = nb2[l*NTt + t];
            for (int c = 0; c < 128; c++) a = fmaf(h[rl*128 + c], W2[c], a);
            lg[rl*NTt + t] = a;
        }
        __syncthreads();
        if (tid < 32) {
            float best = lg[tid*NTt]; int bx = 0;
            #pragma unroll
            for (int t = 1; t < NTt; t++) {
                float v = lg[tid*NTt + t];
                if (v > best) { best = v; bx = t; }
            }
            float second = -1e30f;
            #pragma unroll
            for (int t = 0; t < NTt; t++) {
                float v = lg[tid*NTt + t];
                if (t != bx && v > second) second = v;
            }
            bi[tid] = bx;
            flags[tid] = (best - second < TAU);
        }
        __syncthreads();
        for (int r = 0; r < 4; r++) {
            int rl = rbase + r;
            if (!flags[rl]) continue;
            int row = row0 + rl;
            int b = row / Nn, n = row % Nn;
            const float* W1 = g_NW1T + l*16384;
            double accd[4];
            #pragma unroll
            for (int q = 0; q < 4; q++) accd[q] = (double)nb1[l*128 + lane + 32*q];
            for (int o = 0; o < 128; o++) {
                double gv = g_Sd[(b*Rr + n)*128 + o] * g_a[o] + 38.0 * g_c0[o];
                #pragma unroll
                for (int q = 0; q < 4; q++)
                    accd[q] = fma(gv, (double)W1[o*128 + lane + 32*q], accd[q]);
            }
            double hd[4];
            #pragma unroll
            for (int q = 0; q < 4; q++) hd[q] = tanh(accd[q]);
            double best = -1e300; int bx = 0;
            for (int t = 0; t < NTt; t++) {
                const float* W2 = nw2 + (l*NTt + t)*128;
                double p = 0.0;
                #pragma unroll
                for (int q = 0; q < 4; q++) p = fma(hd[q], (double)W2[lane + 32*q], p);
                #pragma unroll
                for (int s = 16; s > 0; s >>= 1) p += __shfl_down_sync(0xffffffffu, p, s);
                if (lane == 0) {
                    p += (double)nb2[l*NTt + t];
                    if (p > best) { best = p; bx = t; }
                }
            }
            if (lane == 0) bi[rl] = bx;
        }
        __syncthreads();
        if (tid < 32) P[tid] += bi[tid];
    }
    __syncthreads();
    for (int pp = tid; pp < 32*NTt; pp += 256) {
        int rl = pp / NTt, j = pp % NTt;
        int row = row0 + rl;
        int p = P[rl] % NTt;
        out[row*NTt + j] = x_deq[row*NTt + ((j - p + 18) % NTt)];
    }
}

extern "C" void kernel_launch(void* const* d_in, const int* in_sizes, int n_in,
                              void* d_out, int out_size) {
    const float* x       = (const float*)d_in[0];
    const float* adj     = (const float*)d_in[1];
    const float* x_deq   = (const float*)d_in[2];
    const float* adj_deq = (const float*)d_in[3];
    const void*  mn      = d_in[4];
    const void*  me      = d_in[5];
    const int*   isel    = (const int*)d_in[6];
    const float* embw    = (const float*)d_in[7];
    const float* gc1     = (const float*)d_in[8];
    const float* gc2     = (const float*)d_in[9];
    const float* gc3     = (const float*)d_in[10];
    const float* gamma   = (const float*)d_in[11];
    const float* beta    = (const float*)d_in[12];
    const float* nw1     = (const float*)d_in[13];
    const float* nb1     = (const float*)d_in[14];
    const float* nw2     = (const float*)d_in[15];
    const float* nb2     = (const float*)d_in[16];
    const float* ew1     = (const float*)d_in[17];
    const float* eb1     = (const float*)d_in[18];
    const float* ew2     = (const float*)d_in[19];
    const float* eb2     = (const float*)d_in[20];
    float* out = (float*)d_out;

    cudaFuncSetAttribute(k_rgcn, cudaFuncAttributeMaxDynamicSharedMemorySize, 101376);
    cudaFuncSetAttribute(k_edge_flow, cudaFuncAttributeMaxDynamicSharedMemorySize, 99200);
    cudaFuncSetAttribute(k_node_flow, cudaFuncAttributeMaxDynamicSharedMemorySize, 67072);

    k_init<<<1, 128>>>((const unsigned char*)mn);
    k_prep_w<<<2304, 256>>>(gc2, gc3, ew1, nw1);
    k_prep_ps1<<<16, 384>>>(x, embw, gc1);
    k_rgcn<<<BRr, 256, 101120>>>(adj, mn, me, isel);
    k_stats<<<1, 128>>>(gamma, beta);
    k_node_flow<<<19, 256, 67072>>>(x_deq, nb1, nw2, nb2, out);
    k_edge_flow<<<352, 256, 99200>>>(adj_deq, eb1, ew2, eb2, out);
}

// round 7
// speedup vs baseline: 6.1092x; 1.3457x over previous
#include <cuda_runtime.h>
#include <math.h>

#define BB 16
#define Nn 38
#define NTt 9
#define NEe 703
#define Rr 741
#define BRr (BB*Rr)
#define Ll 12
#define EROWS (BB*NEe)   // 11248
#define NROWS (BB*Nn)    // 608
#define TAU 0.004f

typedef unsigned long long ull;

// ---------------- static device scratch ----------------
__device__ __align__(16) float  g_PS1[BB*Nn*384];
__device__ __align__(16) float  g_W2T[128*384];
__device__ __align__(16) float  g_W3T[128*384];
__device__ __align__(16) float  g_EW1T[Ll*384*128];  // [l][o][c]
__device__ __align__(16) float  g_NW1T[Ll*128*128];  // [l][o][c]
__device__ __align__(16) double g_Sd[BRr*128];
__device__ __align__(16) float  g_sel2[BB*NEe*2*128];
__device__ double g_sum[128];
__device__ double g_sumsq[128];
__device__ double g_a[128];
__device__ double g_c0[128];
__device__ int    g_mode;

__device__ __forceinline__ bool read_mask(const void* p, int i, int mode) {
    if (mode == 0) return ((const unsigned char*)p)[i] != 0;
    if (mode == 1) return ((const float*)p)[i] != 0.0f;
    return ((const int*)p)[i] != 0;
}

// ---- packed f32x2 helpers (lane-wise rounding identical to scalar FFMA) ----
__device__ __forceinline__ ull pack2(float a, float b) {
    ull r; asm("mov.b64 %0, {%1, %2};" : "=l"(r) : "f"(a), "f"(b)); return r;
}
__device__ __forceinline__ void unpack2(ull v, float& x, float& y) {
    asm("mov.b64 {%0, %1}, %2;" : "=f"(x), "=f"(y) : "l"(v));
}
__device__ __forceinline__ void fma2(ull& d, ull a, ull b) {
    asm("fma.rn.f32x2 %0, %1, %2, %3;" : "=l"(d) : "l"(a), "l"(b), "l"(d));
}
__device__ __forceinline__ float f4c(const float4& v, int i) {
    return i == 0 ? v.x : (i == 1 ? v.y : (i == 2 ? v.z : v.w));
}

__global__ void k_init(const unsigned char* __restrict__ mn) {
    int t = threadIdx.x;
    if (t < 128) { g_sum[t] = 0.0; g_sumsq[t] = 0.0; }
    if (t == 0) {
        bool b8 = false, f32 = false;
        for (int i = 0; i < 152; i++) {
            unsigned char v = mn[i];
            if ((i & 3) != 0 && v == 1) b8 = true;
            if ((i & 3) == 3 && v == 0x3f) f32 = true;
        }
        g_mode = b8 ? 0 : (f32 ? 1 : 2);
    }
}

__global__ void k_prep_w(const float* __restrict__ gc2, const float* __restrict__ gc3,
                         const float* __restrict__ ew1, const float* __restrict__ nw1) {
    int i = blockIdx.x * 256 + threadIdx.x;
    if (i < 49152) {
        int k = i / 384, c = i % 384;
        g_W2T[i] = gc2[c*128 + k];
        g_W3T[i] = gc3[c*128 + k];
    }
    if (i < 589824) {
        int l = i / 49152, rem = i % 49152;
        int o = rem / 128, c = rem % 128;
        g_EW1T[i] = ew1[l*49152 + c*384 + o];
    }
    if (i < 196608) {
        int l = i / 16384, rem = i % 16384;
        int o = rem / 128, c = rem % 128;
        g_NW1T[i] = nw1[l*16384 + c*128 + o];
    }
}

__global__ void k_prep_ps1(const float* __restrict__ x, const float* __restrict__ embw,
                           const float* __restrict__ gc1) {
    __shared__ float h0[Nn*NTt];
    int b = blockIdx.x, t = threadIdx.x;
    if (t < Nn*NTt) {
        int j = t / NTt, tt = t % NTt;
        float acc = 0.f;
        #pragma unroll
        for (int u = 0; u < NTt; u++) acc += x[(b*Nn + j)*NTt + u] * embw[tt*NTt + u];
        h0[t] = acc;
    }
    __syncthreads();
    if (t < 384) {
        for (int j = 0; j < Nn; j++) {
            float acc = 0.f;
            #pragma unroll
            for (int u = 0; u < NTt; u++) acc += h0[j*NTt + u] * gc1[t*NTt + u];
            g_PS1[(b*Nn + j)*384 + t] = acc;
        }
    }
}

// ---------------- fused RGCN ----------------
// einsum: out[i][o] = sum_{e,j} sA[e][i][j] * sS[j][e*128+o]   (per-warp: 5 rows x 128 cols)
__device__ __forceinline__ void block_einsum(const float* __restrict__ sA,
                                             const float* __restrict__ sS,
                                             float* __restrict__ sH,
                                             int tx, int ty, bool relu) {
    ull acc[5][2];
    #pragma unroll
    for (int ii = 0; ii < 5; ii++) { acc[ii][0] = 0ull; acc[ii][1] = 0ull; }
    #pragma unroll
    for (int e = 0; e < 3; e++) {
        const float* aE = sA + e*1600 + ty*40;
        const float* sE = sS + e*128 + tx*4;
        #pragma unroll 2
        for (int j = 0; j < 40; j += 4) {
            float4 a4[5];
            #pragma unroll
            for (int ii = 0; ii < 5; ii++) a4[ii] = *(const float4*)(aE + ii*320 + j);
            #pragma unroll
            for (int dj = 0; dj < 4; dj++) {
                ulonglong2 s2 = *(const ulonglong2*)(sE + (j + dj)*384);
                #pragma unroll
                for (int ii = 0; ii < 5; ii++) {
                    float av = f4c(a4[ii], dj);
                    ull aa = pack2(av, av);
                    fma2(acc[ii][0], aa, s2.x);
                    fma2(acc[ii][1], aa, s2.y);
                }
            }
        }
    }
    #pragma unroll
    for (int ii = 0; ii < 5; ii++) {
        int i = ty + 8*ii;
        float4 v;
        unpack2(acc[ii][0], v.x, v.y);
        unpack2(acc[ii][1], v.z, v.w);
        if (relu) {
            v.x = fmaxf(v.x, 0.f); v.y = fmaxf(v.y, 0.f);
            v.z = fmaxf(v.z, 0.f); v.w = fmaxf(v.w, 0.f);
        }
        *(float4*)(sH + i*128 + tx*4) = v;
    }
}

// gemm v2: sS[j][c] = sum_k sH[j][k] * WT[k][c]
// 8 warps = 4 row-groups (10 rows) x 2 col-groups (192 cols); lane owns 6 cols.
// Each (k,c) weight loaded by exactly one warp. k-ascending per element (bit-identical).
__device__ __forceinline__ void block_gemm(const float* __restrict__ WT,
                                           const float* __restrict__ sH,
                                           float* __restrict__ sS,
                                           int tx, int ty) {
    int rg = ty >> 1, cg = ty & 1;
    int colb = cg*192 + tx*6;
    const float* wb = WT + colb;
    const float* hb = sH + rg*10*128;
    ull acc[10][3];
    #pragma unroll
    for (int r = 0; r < 10; r++) { acc[r][0] = 0ull; acc[r][1] = 0ull; acc[r][2] = 0ull; }
    #pragma unroll 1
    for (int k = 0; k < 128; k += 4) {
        float4 h4[10];
        #pragma unroll
        for (int r = 0; r < 10; r++) h4[r] = *(const float4*)(hb + r*128 + k);
        #pragma unroll
        for (int dk = 0; dk < 4; dk++) {
            const ull* wp = (const ull*)(wb + (k + dk)*384);
            ull w0 = wp[0], w1 = wp[1], w2v = wp[2];
            #pragma unroll
            for (int r = 0; r < 10; r++) {
                float hv = f4c(h4[r], dk);
                ull hh = pack2(hv, hv);
                fma2(acc[r][0], hh, w0);
                fma2(acc[r][1], hh, w1);
                fma2(acc[r][2], hh, w2v);
            }
        }
    }
    #pragma unroll
    for (int r = 0; r < 10; r++) {
        ull* op = (ull*)(sS + (rg*10 + r)*384 + colb);
        op[0] = acc[r][0]; op[1] = acc[r][1]; op[2] = acc[r][2];
    }
}

__global__ __launch_bounds__(256, 2) void k_rgcn(
    const float* __restrict__ adj, const void* __restrict__ maskn,
    const void* __restrict__ maske, const int* __restrict__ isel)
{
    extern __shared__ float sm[];
    float* sA = sm;            // 3*40*40 = 4800
    float* sS = sm + 4800;     // 40*384 = 15360 (rows 38,39 stay zero)
    float* sH = sm + 20160;    // 40*128 = 5120
    int tid = threadIdx.x;
    int b = blockIdx.x / Rr, r = blockIdx.x % Rr;
    int mode = g_mode;

    for (int idx = tid; idx < 3*40*40; idx += 256) {
        int j = idx % 40;
        int i = (idx / 40) % 40;
        int e = idx / 1600;
        float v = 0.f;
        if (i < Nn && j < Nn && read_mask(maske, r*1444 + i*38 + j, mode))
            v = adj[((b*4 + e)*38 + i)*38 + j];
        sA[idx] = v;
    }
    for (int idx = tid; idx < 40*384; idx += 256) {
        int j = idx / 384, c = idx % 384;
        float v = 0.f;
        if (j < Nn && read_mask(maskn, r*38 + j, mode))
            v = g_PS1[(b*Nn + j)*384 + c];
        sS[idx] = v;
    }
    __syncthreads();

    int tx = tid & 31, ty = tid >> 5;
    block_einsum(sA, sS, sH, tx, ty, true);   __syncthreads();
    block_gemm(g_W2T, sH, sS, tx, ty);        __syncthreads();
    block_einsum(sA, sS, sH, tx, ty, true);   __syncthreads();
    block_gemm(g_W3T, sH, sS, tx, ty);        __syncthreads();
    block_einsum(sA, sS, sH, tx, ty, false);  __syncthreads();

    if (tid < 128) {
        double s = 0.0, sq = 0.0;
        for (int i = 0; i < Nn; i++) {
            double v = (double)sH[i*128 + tid];
            s += v; sq += v*v;
        }
        g_Sd[blockIdx.x*128 + tid] = s;
        atomicAdd(&g_sum[tid], s);
        atomicAdd(&g_sumsq[tid], sq);
    }
    if (r >= Nn) {
        int k = r - Nn;
        int o = tid & 127, sl = tid >> 7;
        int node = isel[k*2 + sl];
        g_sel2[((b*NEe + k)*2 + sl)*128 + o] = sH[node*128 + o];
    }
}

__global__ void k_stats(const float* __restrict__ gamma, const float* __restrict__ beta) {
    int o = threadIdx.x;
    if (o < 128) {
        const double cnt = (double)(BRr * Nn);
        double m   = g_sum[o] / cnt;
        double var = g_sumsq[o] / cnt - m*m;
        double inv = 1.0 / sqrt(var + 1e-5);
        double a = inv * (double)gamma[o];
        g_a[o]  = a;
        g_c0[o] = (double)beta[o] - m * a;
    }
}

// ---------------- flow kernels: fp32 fast path + fp64 fallback on small gaps ----------------
__global__ __launch_bounds__(256) void k_edge_flow(
    const float* __restrict__ adj_deq, const float* __restrict__ eb1,
    const float* __restrict__ ew2, const float* __restrict__ eb2,
    float* __restrict__ out)
{
    extern __shared__ float fsm[];
    float* sg = fsm;               // 32*384
    float* wt = fsm + 12288;       // 64*128
    float* h  = fsm + 20480;       // 32*128
    float* lg = fsm + 24576;       // 32*4
    int* bi    = (int*)(fsm + 24704);
    int* P     = bi + 32;
    int* flags = bi + 64;
    int tid = threadIdx.x;
    int row0 = blockIdx.x * 32;

    for (int idx = tid; idx < 32*384; idx += 256) {
        int rl = idx / 384, o = idx % 384;
        int row = row0 + rl;
        double v = 0.0;
        if (row < EROWS) {
            int b = row / NEe, k = row % NEe;
            if (o < 256) {
                int oo = o & 127;
                v = (double)g_sel2[(b*NEe + k)*256 + o] * g_a[oo] + g_c0[oo];
            } else {
                int oo = o - 256;
                v = g_Sd[(b*Rr + Nn + k)*128 + oo] * g_a[oo] + 38.0 * g_c0[oo];
            }
        }
        sg[idx] = (float)v;
    }
    if (tid < 32) P[tid] = 0;

    int wrp = tid >> 5, lane = tid & 31;
    int rbase = wrp * 4;
    for (int l = 0; l < Ll; l++) {
        ull acc[4][2];
        {
            float b0 = eb1[l*128 + lane*4+0], b1 = eb1[l*128 + lane*4+1];
            float b2 = eb1[l*128 + lane*4+2], b3 = eb1[l*128 + lane*4+3];
            ull p01 = pack2(b0, b1), p23 = pack2(b2, b3);
            #pragma unroll
            for (int r = 0; r < 4; r++) { acc[r][0] = p01; acc[r][1] = p23; }
        }
        for (int tile = 0; tile < 6; tile++) {
            __syncthreads();
            const float* src = g_EW1T + l*49152 + tile*8192;
            for (int i = tid*4; i < 8192; i += 1024)
                *(float4*)(wt + i) = *(const float4*)(src + i);
            __syncthreads();
            #pragma unroll 2
            for (int oo = 0; oo < 64; oo += 4) {
                float4 s4[4];
                #pragma unroll
                for (int r = 0; r < 4; r++)
                    s4[r] = *(const float4*)(sg + (rbase + r)*384 + tile*64 + oo);
                #pragma unroll
                for (int doo = 0; doo < 4; doo++) {
                    ulonglong2 w2 = *(const ulonglong2*)(wt + (oo + doo)*128 + lane*4);
                    #pragma unroll
                    for (int r = 0; r < 4; r++) {
                        float sv = f4c(s4[r], doo);
                        ull ss = pack2(sv, sv);
                        fma2(acc[r][0], ss, w2.x);
                        fma2(acc[r][1], ss, w2.y);
                    }
                }
            }
        }
        #pragma unroll
        for (int r = 0; r < 4; r++) {
            float a0, a1, a2, a3;
            unpack2(acc[r][0], a0, a1);
            unpack2(acc[r][1], a2, a3);
            float* hp = h + (rbase + r)*128 + lane*4;
            hp[0] = tanhf(a0); hp[1] = tanhf(a1); hp[2] = tanhf(a2); hp[3] = tanhf(a3);
        }
        __syncthreads();
        if (tid < 128) {
            int rl = tid >> 2, t = tid & 3;
            const float* W2 = ew2 + (l*4 + t)*128;
            float a = eb2[l*4 + t];
            for (int c = 0; c < 128; c++) a = fmaf(h[rl*128 + c], W2[c], a);
            lg[rl*4 + t] = a;
        }
        __syncthreads();
        if (tid < 32) {
            float l0 = lg[tid*4], l1 = lg[tid*4+1], l2 = lg[tid*4+2], l3 = lg[tid*4+3];
            float best = l0; int bx = 0;
            if (l1 > best) { best = l1; bx = 1; }
            if (l2 > best) { best = l2; bx = 2; }
            if (l3 > best) { best = l3; bx = 3; }
            float second = -1e30f;
            if (bx != 0 && l0 > second) second = l0;
            if (bx != 1 && l1 > second) second = l1;
            if (bx != 2 && l2 > second) second = l2;
            if (bx != 3 && l3 > second) second = l3;
            bi[tid] = bx;
            flags[tid] = (best - second < TAU) && (row0 + tid < EROWS);
        }
        __syncthreads();
        for (int r = 0; r < 4; r++) {
            int rl = rbase + r;
            if (!flags[rl]) continue;
            int row = row0 + rl;
            int b = row / NEe, k = row % NEe;
            const float* W1 = g_EW1T + l*49152;
            double accd[4];
            #pragma unroll
            for (int q = 0; q < 4; q++) accd[q] = (double)eb1[l*128 + lane + 32*q];
            for (int o = 0; o < 384; o++) {
                double gv;
                if (o < 256) {
                    int oo = o & 127;
                    gv = (double)g_sel2[(b*NEe + k)*256 + o] * g_a[oo] + g_c0[oo];
                } else {
                    int oo = o - 256;
                    gv = g_Sd[(b*Rr + Nn + k)*128 + oo] * g_a[oo] + 38.0 * g_c0[oo];
                }
                #pragma unroll
                for (int q = 0; q < 4; q++)
                    accd[q] = fma(gv, (double)W1[o*128 + lane + 32*q], accd[q]);
            }
            double hd[4];
            #pragma unroll
            for (int q = 0; q < 4; q++) hd[q] = tanh(accd[q]);
            double lgd[4];
            #pragma unroll
            for (int t = 0; t < 4; t++) {
                const float* W2 = ew2 + (l*4 + t)*128;
                double p = 0.0;
                #pragma unroll
                for (int q = 0; q < 4; q++) p = fma(hd[q], (double)W2[lane + 32*q], p);
                #pragma unroll
                for (int s = 16; s > 0; s >>= 1) p += __shfl_down_sync(0xffffffffu, p, s);
                lgd[t] = p;
            }
            if (lane == 0) {
                #pragma unroll
                for (int t = 0; t < 4; t++) lgd[t] += (double)eb2[l*4 + t];
                double best = lgd[0]; int bx = 0;
                if (lgd[1] > best) { best = lgd[1]; bx = 1; }
                if (lgd[2] > best) { best = lgd[2]; bx = 2; }
                if (lgd[3] > best) { best = lgd[3]; bx = 3; }
                bi[rl] = bx;
            }
        }
        __syncthreads();
        if (tid < 32) P[tid] += bi[tid];
    }
    __syncthreads();
    if (tid < 128) {
        int rl = tid >> 2, j = tid & 3;
        int row = row0 + rl;
        if (row < EROWS) {
            int p = P[rl] & 3;
            out[NROWS*NTt + row*4 + j] = adj_deq[row*4 + ((j - p + 4) & 3)];
        }
    }
}

__global__ __launch_bounds__(256) void k_node_flow(
    const float* __restrict__ x_deq, const float* __restrict__ nb1,
    const float* __restrict__ nw2, const float* __restrict__ nb2,
    float* __restrict__ out)
{
    extern __shared__ float fsm[];
    float* sg = fsm;               // 32*128
    float* wt = fsm + 4096;        // 64*128
    float* h  = fsm + 12288;       // 32*128
    float* lg = fsm + 16384;       // 32*9
    int* bi    = (int*)(fsm + 16672);
    int* P     = bi + 32;
    int* flags = bi + 64;
    int tid = threadIdx.x;
    int row0 = blockIdx.x * 32;

    for (int idx = tid; idx < 32*128; idx += 256) {
        int rl = idx >> 7, o = idx & 127;
        int row = row0 + rl;
        int b = row / Nn, n = row % Nn;
        sg[idx] = (float)(g_Sd[(b*Rr + n)*128 + o] * g_a[o] + 38.0 * g_c0[o]);
    }
    if (tid < 32) P[tid] = 0;

    int wrp = tid >> 5, lane = tid & 31;
    int rbase = wrp * 4;
    for (int l = 0; l < Ll; l++) {
        float acc[4][4];
        #pragma unroll
        for (int q = 0; q < 4; q++) {
            float bq = nb1[l*128 + lane*4 + q];
            acc[0][q] = bq; acc[1][q] = bq; acc[2][q] = bq; acc[3][q] = bq;
        }
        for (int tile = 0; tile < 2; tile++) {
            __syncthreads();
            const float* src = g_NW1T + l*16384 + tile*8192;
            for (int i = tid*4; i < 8192; i += 1024)
                *(float4*)(wt + i) = *(const float4*)(src + i);
            __syncthreads();
            #pragma unroll 2
            for (int oo = 0; oo < 64; oo++) {
                float4 w4 = *(const float4*)(wt + oo*128 + lane*4);
                #pragma unroll
                for (int r = 0; r < 4; r++) {
                    float s = sg[(rbase + r)*128 + tile*64 + oo];
                    acc[r][0] = fmaf(s, w4.x, acc[r][0]);
                    acc[r][1] = fmaf(s, w4.y, acc[r][1]);
                    acc[r][2] = fmaf(s, w4.z, acc[r][2]);
                    acc[r][3] = fmaf(s, w4.w, acc[r][3]);
                }
            }
        }
        #pragma unroll
        for (int r = 0; r < 4; r++)
            #pragma unroll
            for (int q = 0; q < 4; q++)
                h[(rbase + r)*128 + lane*4 + q] = tanhf(acc[r][q]);
        __syncthreads();
        for (int pp = tid; pp < 32*NTt; pp += 256) {
            int rl = pp / NTt, t = pp % NTt;
            const float* W2 = nw2 + (l*NTt + t)*128;
            float a = nb2[l*NTt + t];
            for (int c = 0; c < 128; c++) a = fmaf(h[rl*128 + c], W2[c], a);
            lg[rl*NTt + t] = a;
        }
        __syncthreads();
        if (tid < 32) {
            float best = lg[tid*NTt]; int bx = 0;
            #pragma unroll
            for (int t = 1; t < NTt; t++) {
                float v = lg[tid*NTt + t];
                if (v > best) { best = v; bx = t; }
            }
            float second = -1e30f;
            #pragma unroll
            for (int t = 0; t < NTt; t++) {
                float v = lg[tid*NTt + t];
                if (t != bx && v > second) second = v;
            }
            bi[tid] = bx;
            flags[tid] = (best - second < TAU);
        }
        __syncthreads();
        for (int r = 0; r < 4; r++) {
            int rl = rbase + r;
            if (!flags[rl]) continue;
            int row = row0 + rl;
            int b = row / Nn, n = row % Nn;
            const float* W1 = g_NW1T + l*16384;
            double accd[4];
            #pragma unroll
            for (int q = 0; q < 4; q++) accd[q] = (double)nb1[l*128 + lane + 32*q];
            for (int o = 0; o < 128; o++) {
                double gv = g_Sd[(b*Rr + n)*128 + o] * g_a[o] + 38.0 * g_c0[o];
                #pragma unroll
                for (int q = 0; q < 4; q++)
                    accd[q] = fma(gv, (double)W1[o*128 + lane + 32*q], accd[q]);
            }
            double hd[4];
            #pragma unroll
            for (int q = 0; q < 4; q++) hd[q] = tanh(accd[q]);
            double best = -1e300; int bx = 0;
            for (int t = 0; t < NTt; t++) {
                const float* W2 = nw2 + (l*NTt + t)*128;
                double p = 0.0;
                #pragma unroll
                for (int q = 0; q < 4; q++) p = fma(hd[q], (double)W2[lane + 32*q], p);
                #pragma unroll
                for (int s = 16; s > 0; s >>= 1) p += __shfl_down_sync(0xffffffffu, p, s);
                if (lane == 0) {
                    p += (double)nb2[l*NTt + t];
                    if (p > best) { best = p; bx = t; }
                }
            }
            if (lane == 0) bi[rl] = bx;
        }
        __syncthreads();
        if (tid < 32) P[tid] += bi[tid];
    }
    __syncthreads();
    for (int pp = tid; pp < 32*NTt; pp += 256) {
        int rl = pp / NTt, j = pp % NTt;
        int row = row0 + rl;
        int p = P[rl] % NTt;
        out[row*NTt + j] = x_deq[row*NTt + ((j - p + 18) % NTt)];
    }
}

extern "C" void kernel_launch(void* const* d_in, const int* in_sizes, int n_in,
                              void* d_out, int out_size) {
    const float* x       = (const float*)d_in[0];
    const float* adj     = (const float*)d_in[1];
    const float* x_deq   = (const float*)d_in[2];
    const float* adj_deq = (const float*)d_in[3];
    const void*  mn      = d_in[4];
    const void*  me      = d_in[5];
    const int*   isel    = (const int*)d_in[6];
    const float* embw    = (const float*)d_in[7];
    const float* gc1     = (const float*)d_in[8];
    const float* gc2     = (const float*)d_in[9];
    const float* gc3     = (const float*)d_in[10];
    const float* gamma   = (const float*)d_in[11];
    const float* beta    = (const float*)d_in[12];
    const float* nw1     = (const float*)d_in[13];
    const float* nb1     = (const float*)d_in[14];
    const float* nw2     = (const float*)d_in[15];
    const float* nb2     = (const float*)d_in[16];
    const float* ew1     = (const float*)d_in[17];
    const float* eb1     = (const float*)d_in[18];
    const float* ew2     = (const float*)d_in[19];
    const float* eb2     = (const float*)d_in[20];
    float* out = (float*)d_out;

    cudaFuncSetAttribute(k_rgcn, cudaFuncAttributeMaxDynamicSharedMemorySize, 101376);
    cudaFuncSetAttribute(k_edge_flow, cudaFuncAttributeMaxDynamicSharedMemorySize, 99200);
    cudaFuncSetAttribute(k_node_flow, cudaFuncAttributeMaxDynamicSharedMemorySize, 67072);

    k_init<<<1, 128>>>((const unsigned char*)mn);
    k_prep_w<<<2304, 256>>>(gc2, gc3, ew1, nw1);
    k_prep_ps1<<<16, 384>>>(x, embw, gc1);
    k_rgcn<<<BRr, 256, 101120>>>(adj, mn, me, isel);
    k_stats<<<1, 128>>>(gamma, beta);
    k_node_flow<<<19, 256, 67072>>>(x_deq, nb1, nw2, nb2, out);
    k_edge_flow<<<352, 256, 99200>>>(adj_deq, eb1, ew2, eb2, out);
}

// round 8
// speedup vs baseline: 6.1105x; 1.0002x over previous
#include <cuda_runtime.h>
#include <math.h>

#define BB 16
#define Nn 38
#define NTt 9
#define NEe 703
#define Rr 741
#define BRr (BB*Rr)
#define Ll 12
#define EROWS (BB*NEe)   // 11248
#define NROWS (BB*Nn)    // 608
#define TAU 0.004f

typedef unsigned long long ull;

// ---------------- static device scratch ----------------
__device__ __align__(16) float  g_PS1[BB*Nn*384];
__device__ __align__(16) float  g_W2T[128*384];
__device__ __align__(16) float  g_W3T[128*384];
__device__ __align__(16) float  g_EW1T[Ll*384*128];  // [l][o][c]
__device__ __align__(16) float  g_NW1T[Ll*128*128];  // [l][o][c]
__device__ __align__(16) double g_Sd[BRr*128];
__device__ __align__(16) float  g_sel2[BB*NEe*2*128];
__device__ double g_sum[128];
__device__ double g_sumsq[128];
__device__ double g_a[128];
__device__ double g_c0[128];
__device__ int    g_mode;

__device__ __forceinline__ bool read_mask(const void* p, int i, int mode) {
    if (mode == 0) return ((const unsigned char*)p)[i] != 0;
    if (mode == 1) return ((const float*)p)[i] != 0.0f;
    return ((const int*)p)[i] != 0;
}

// ---- packed f32x2 helpers (lane-wise rounding identical to scalar FFMA) ----
__device__ __forceinline__ ull pack2(float a, float b) {
    ull r; asm("mov.b64 %0, {%1, %2};" : "=l"(r) : "f"(a), "f"(b)); return r;
}
__device__ __forceinline__ void unpack2(ull v, float& x, float& y) {
    asm("mov.b64 {%0, %1}, %2;" : "=f"(x), "=f"(y) : "l"(v));
}
__device__ __forceinline__ void fma2(ull& d, ull a, ull b) {
    asm("fma.rn.f32x2 %0, %1, %2, %3;" : "=l"(d) : "l"(a), "l"(b), "l"(d));
}
__device__ __forceinline__ float f4c(const float4& v, int i) {
    return i == 0 ? v.x : (i == 1 ? v.y : (i == 2 ? v.z : v.w));
}

__global__ void k_init(const unsigned char* __restrict__ mn) {
    int t = threadIdx.x;
    if (t < 128) { g_sum[t] = 0.0; g_sumsq[t] = 0.0; }
    if (t == 0) {
        bool b8 = false, f32 = false;
        for (int i = 0; i < 152; i++) {
            unsigned char v = mn[i];
            if ((i & 3) != 0 && v == 1) b8 = true;
            if ((i & 3) == 3 && v == 0x3f) f32 = true;
        }
        g_mode = b8 ? 0 : (f32 ? 1 : 2);
    }
}

__global__ void k_prep_w(const float* __restrict__ gc2, const float* __restrict__ gc3,
                         const float* __restrict__ ew1, const float* __restrict__ nw1) {
    int i = blockIdx.x * 256 + threadIdx.x;
    if (i < 49152) {
        int k = i / 384, c = i % 384;
        g_W2T[i] = gc2[c*128 + k];
        g_W3T[i] = gc3[c*128 + k];
    }
    if (i < 589824) {
        int l = i / 49152, rem = i % 49152;
        int o = rem / 128, c = rem % 128;
        g_EW1T[i] = ew1[l*49152 + c*384 + o];
    }
    if (i < 196608) {
        int l = i / 16384, rem = i % 16384;
        int o = rem / 128, c = rem % 128;
        g_NW1T[i] = nw1[l*16384 + c*128 + o];
    }
}

__global__ void k_prep_ps1(const float* __restrict__ x, const float* __restrict__ embw,
                           const float* __restrict__ gc1) {
    __shared__ float h0[Nn*NTt];
    int b = blockIdx.x, t = threadIdx.x;
    if (t < Nn*NTt) {
        int j = t / NTt, tt = t % NTt;
        float acc = 0.f;
        #pragma unroll
        for (int u = 0; u < NTt; u++) acc += x[(b*Nn + j)*NTt + u] * embw[tt*NTt + u];
        h0[t] = acc;
    }
    __syncthreads();
    if (t < 384) {
        for (int j = 0; j < Nn; j++) {
            float acc = 0.f;
            #pragma unroll
            for (int u = 0; u < NTt; u++) acc += h0[j*NTt + u] * gc1[t*NTt + u];
            g_PS1[(b*Nn + j)*384 + t] = acc;
        }
    }
}

// ---------------- fused RGCN ----------------
// einsum v3: out[i][o] = sum_{e,j} sA[e][i][j] * sS[j][e*128+o]
// 8 warps = 4 row-groups (10 rows) x 2 col-groups (64 cols); lane owns 2 adjacent cols.
// sS loads are coalesced LDS.64, no cross-warp duplication within a col-group row.
// Per-output accumulation: e ascending, j ascending -> bit-identical to prior rounds.
__device__ __forceinline__ void block_einsum(const float* __restrict__ sA,
                                             const float* __restrict__ sS,
                                             float* __restrict__ sH,
                                             int tx, int ty, bool relu) {
    int rg = ty >> 1, cg = ty & 1;
    ull acc[10];
    #pragma unroll
    for (int r = 0; r < 10; r++) acc[r] = 0ull;
    #pragma unroll
    for (int e = 0; e < 3; e++) {
        const float* aE = sA + e*1600 + rg*10*40;
        const float* sE = sS + e*128 + cg*64 + tx*2;
        #pragma unroll 2
        for (int j = 0; j < 40; j += 4) {
            float4 a4[10];
            #pragma unroll
            for (int r = 0; r < 10; r++) a4[r] = *(const float4*)(aE + r*40 + j);
            #pragma unroll
            for (int dj = 0; dj < 4; dj++) {
                ull s2 = *(const ull*)(sE + (j + dj)*384);
                #pragma unroll
                for (int r = 0; r < 10; r++) {
                    float av = f4c(a4[r], dj);
                    fma2(acc[r], pack2(av, av), s2);
                }
            }
        }
    }
    #pragma unroll
    for (int r = 0; r < 10; r++) {
        float vx, vy;
        unpack2(acc[r], vx, vy);
        if (relu) { vx = fmaxf(vx, 0.f); vy = fmaxf(vy, 0.f); }
        *(ull*)(sH + (rg*10 + r)*128 + cg*64 + tx*2) = pack2(vx, vy);
    }
}

// gemm v2b: sS[j][c] = sum_k sH[j][k] * WT[k][c]
// 8 warps = 4 row-groups (10 rows) x 2 col-groups (192 cols as 3 segments of 64);
// lane owns 2 adjacent cols per segment -> all weight loads coalesced LDS.64.
// k ascending per output element -> bit-identical.
__device__ __forceinline__ void block_gemm(const float* __restrict__ WT,
                                           const float* __restrict__ sH,
                                           float* __restrict__ sS,
                                           int tx, int ty) {
    int rg = ty >> 1, cg = ty & 1;
    int colb = cg*192 + tx*2;
    const float* wb = WT + colb;
    const float* hb = sH + rg*10*128;
    ull acc[10][3];
    #pragma unroll
    for (int r = 0; r < 10; r++) { acc[r][0] = 0ull; acc[r][1] = 0ull; acc[r][2] = 0ull; }
    #pragma unroll 1
    for (int k = 0; k < 128; k += 4) {
        float4 h4[10];
        #pragma unroll
        for (int r = 0; r < 10; r++) h4[r] = *(const float4*)(hb + r*128 + k);
        #pragma unroll
        for (int dk = 0; dk < 4; dk++) {
            const float* wr = wb + (k + dk)*384;
            ull w0 = *(const ull*)(wr);
            ull w1 = *(const ull*)(wr + 64);
            ull w2v = *(const ull*)(wr + 128);
            #pragma unroll
            for (int r = 0; r < 10; r++) {
                float hv = f4c(h4[r], dk);
                ull hh = pack2(hv, hv);
                fma2(acc[r][0], hh, w0);
                fma2(acc[r][1], hh, w1);
                fma2(acc[r][2], hh, w2v);
            }
        }
    }
    #pragma unroll
    for (int r = 0; r < 10; r++) {
        float* ob = sS + (rg*10 + r)*384 + colb;
        *(ull*)(ob)       = acc[r][0];
        *(ull*)(ob + 64)  = acc[r][1];
        *(ull*)(ob + 128) = acc[r][2];
    }
}

__global__ __launch_bounds__(256, 2) void k_rgcn(
    const float* __restrict__ adj, const void* __restrict__ maskn,
    const void* __restrict__ maske, const int* __restrict__ isel)
{
    extern __shared__ float sm[];
    float* sA = sm;            // 3*40*40 = 4800
    float* sS = sm + 4800;     // 40*384 = 15360 (rows 38,39 stay zero)
    float* sH = sm + 20160;    // 40*128 = 5120
    int tid = threadIdx.x;
    int b = blockIdx.x / Rr, r = blockIdx.x % Rr;
    int mode = g_mode;

    for (int idx = tid; idx < 3*40*40; idx += 256) {
        int j = idx % 40;
        int i = (idx / 40) % 40;
        int e = idx / 1600;
        float v = 0.f;
        if (i < Nn && j < Nn && read_mask(maske, r*1444 + i*38 + j, mode))
            v = adj[((b*4 + e)*38 + i)*38 + j];
        sA[idx] = v;
    }
    for (int idx = tid; idx < 40*384; idx += 256) {
        int j = idx / 384, c = idx % 384;
        float v = 0.f;
        if (j < Nn && read_mask(maskn, r*38 + j, mode))
            v = g_PS1[(b*Nn + j)*384 + c];
        sS[idx] = v;
    }
    __syncthreads();

    int tx = tid & 31, ty = tid >> 5;
    block_einsum(sA, sS, sH, tx, ty, true);   __syncthreads();
    block_gemm(g_W2T, sH, sS, tx, ty);        __syncthreads();
    block_einsum(sA, sS, sH, tx, ty, true);   __syncthreads();
    block_gemm(g_W3T, sH, sS, tx, ty);        __syncthreads();
    block_einsum(sA, sS, sH, tx, ty, false);  __syncthreads();

    if (tid < 128) {
        double s = 0.0, sq = 0.0;
        for (int i = 0; i < Nn; i++) {
            double v = (double)sH[i*128 + tid];
            s += v; sq += v*v;
        }
        g_Sd[blockIdx.x*128 + tid] = s;
        atomicAdd(&g_sum[tid], s);
        atomicAdd(&g_sumsq[tid], sq);
    }
    if (r >= Nn) {
        int k = r - Nn;
        int o = tid & 127, sl = tid >> 7;
        int node = isel[k*2 + sl];
        g_sel2[((b*NEe + k)*2 + sl)*128 + o] = sH[node*128 + o];
    }
}

__global__ void k_stats(const float* __restrict__ gamma, const float* __restrict__ beta) {
    int o = threadIdx.x;
    if (o < 128) {
        const double cnt = (double)(BRr * Nn);
        double m   = g_sum[o] / cnt;
        double var = g_sumsq[o] / cnt - m*m;
        double inv = 1.0 / sqrt(var + 1e-5);
        double a = inv * (double)gamma[o];
        g_a[o]  = a;
        g_c0[o] = (double)beta[o] - m * a;
    }
}

// ---------------- flow kernels: fp32 fast path + fp64 fallback on small gaps ----------------
__global__ __launch_bounds__(256) void k_edge_flow(
    const float* __restrict__ adj_deq, const float* __restrict__ eb1,
    const float* __restrict__ ew2, const float* __restrict__ eb2,
    float* __restrict__ out)
{
    extern __shared__ float fsm[];
    float* sg = fsm;               // 32*384
    float* wt = fsm + 12288;       // 64*128
    float* h  = fsm + 20480;       // 32*128
    float* lg = fsm + 24576;       // 32*4
    int* bi    = (int*)(fsm + 24704);
    int* P     = bi + 32;
    int* flags = bi + 64;
    int tid = threadIdx.x;
    int row0 = blockIdx.x * 32;

    for (int idx = tid; idx < 32*384; idx += 256) {
        int rl = idx / 384, o = idx % 384;
        int row = row0 + rl;
        double v = 0.0;
        if (row < EROWS) {
            int b = row / NEe, k = row % NEe;
            if (o < 256) {
                int oo = o & 127;
                v = (double)g_sel2[(b*NEe + k)*256 + o] * g_a[oo] + g_c0[oo];
            } else {
                int oo = o - 256;
                v = g_Sd[(b*Rr + Nn + k)*128 + oo] * g_a[oo] + 38.0 * g_c0[oo];
            }
        }
        sg[idx] = (float)v;
    }
    if (tid < 32) P[tid] = 0;

    int wrp = tid >> 5, lane = tid & 31;
    int rbase = wrp * 4;
    for (int l = 0; l < Ll; l++) {
        ull acc[4][2];
        {
            float b0 = eb1[l*128 + lane*4+0], b1 = eb1[l*128 + lane*4+1];
            float b2 = eb1[l*128 + lane*4+2], b3 = eb1[l*128 + lane*4+3];
            ull p01 = pack2(b0, b1), p23 = pack2(b2, b3);
            #pragma unroll
            for (int r = 0; r < 4; r++) { acc[r][0] = p01; acc[r][1] = p23; }
        }
        for (int tile = 0; tile < 6; tile++) {
            __syncthreads();
            const float* src = g_EW1T + l*49152 + tile*8192;
            for (int i = tid*4; i < 8192; i += 1024)
                *(float4*)(wt + i) = *(const float4*)(src + i);
            __syncthreads();
            #pragma unroll 2
            for (int oo = 0; oo < 64; oo += 4) {
                float4 s4[4];
                #pragma unroll
                for (int r = 0; r < 4; r++)
                    s4[r] = *(const float4*)(sg + (rbase + r)*384 + tile*64 + oo);
                #pragma unroll
                for (int doo = 0; doo < 4; doo++) {
                    ulonglong2 w2 = *(const ulonglong2*)(wt + (oo + doo)*128 + lane*4);
                    #pragma unroll
                    for (int r = 0; r < 4; r++) {
                        float sv = f4c(s4[r], doo);
                        ull ss = pack2(sv, sv);
                        fma2(acc[r][0], ss, w2.x);
                        fma2(acc[r][1], ss, w2.y);
                    }
                }
            }
        }
        #pragma unroll
        for (int r = 0; r < 4; r++) {
            float a0, a1, a2, a3;
            unpack2(acc[r][0], a0, a1);
            unpack2(acc[r][1], a2, a3);
            float* hp = h + (rbase + r)*128 + lane*4;
            hp[0] = tanhf(a0); hp[1] = tanhf(a1); hp[2] = tanhf(a2); hp[3] = tanhf(a3);
        }
        __syncthreads();
        if (tid < 128) {
            int rl = tid >> 2, t = tid & 3;
            const float* W2 = ew2 + (l*4 + t)*128;
            float a = eb2[l*4 + t];
            for (int c = 0; c < 128; c++) a = fmaf(h[rl*128 + c], W2[c], a);
            lg[rl*4 + t] = a;
        }
        __syncthreads();
        if (tid < 32) {
            float l0 = lg[tid*4], l1 = lg[tid*4+1], l2 = lg[tid*4+2], l3 = lg[tid*4+3];
            float best = l0; int bx = 0;
            if (l1 > best) { best = l1; bx = 1; }
            if (l2 > best) { best = l2; bx = 2; }
            if (l3 > best) { best = l3; bx = 3; }
            float second = -1e30f;
            if (bx != 0 && l0 > second) second = l0;
            if (bx != 1 && l1 > second) second = l1;
            if (bx != 2 && l2 > second) second = l2;
            if (bx != 3 && l3 > second) second = l3;
            bi[tid] = bx;
            flags[tid] = (best - second < TAU) && (row0 + tid < EROWS);
        }
        __syncthreads();
        for (int r = 0; r < 4; r++) {
            int rl = rbase + r;
            if (!flags[rl]) continue;
            int row = row0 + rl;
            int b = row / NEe, k = row % NEe;
            const float* W1 = g_EW1T + l*49152;
            double accd[4];
            #pragma unroll
            for (int q = 0; q < 4; q++) accd[q] = (double)eb1[l*128 + lane + 32*q];
            for (int o = 0; o < 384; o++) {
                double gv;
                if (o < 256) {
                    int oo = o & 127;
                    gv = (double)g_sel2[(b*NEe + k)*256 + o] * g_a[oo] + g_c0[oo];
                } else {
                    int oo = o - 256;
                    gv = g_Sd[(b*Rr + Nn + k)*128 + oo] * g_a[oo] + 38.0 * g_c0[oo];
                }
                #pragma unroll
                for (int q = 0; q < 4; q++)
                    accd[q] = fma(gv, (double)W1[o*128 + lane + 32*q], accd[q]);
            }
            double hd[4];
            #pragma unroll
            for (int q = 0; q < 4; q++) hd[q] = tanh(accd[q]);
            double lgd[4];
            #pragma unroll
            for (int t = 0; t < 4; t++) {
                const float* W2 = ew2 + (l*4 + t)*128;
                double p = 0.0;
                #pragma unroll
                for (int q = 0; q < 4; q++) p = fma(hd[q], (double)W2[lane + 32*q], p);
                #pragma unroll
                for (int s = 16; s > 0; s >>= 1) p += __shfl_down_sync(0xffffffffu, p, s);
                lgd[t] = p;
            }
            if (lane == 0) {
                #pragma unroll
                for (int t = 0; t < 4; t++) lgd[t] += (double)eb2[l*4 + t];
                double best = lgd[0]; int bx = 0;
                if (lgd[1] > best) { best = lgd[1]; bx = 1; }
                if (lgd[2] > best) { best = lgd[2]; bx = 2; }
                if (lgd[3] > best) { best = lgd[3]; bx = 3; }
                bi[rl] = bx;
            }
        }
        __syncthreads();
        if (tid < 32) P[tid] += bi[tid];
    }
    __syncthreads();
    if (tid < 128) {
        int rl = tid >> 2, j = tid & 3;
        int row = row0 + rl;
        if (row < EROWS) {
            int p = P[rl] & 3;
            out[NROWS*NTt + row*4 + j] = adj_deq[row*4 + ((j - p + 4) & 3)];
        }
    }
}

__global__ __launch_bounds__(256) void k_node_flow(
    const float* __restrict__ x_deq, const float* __restrict__ nb1,
    const float* __restrict__ nw2, const float* __restrict__ nb2,
    float* __restrict__ out)
{
    extern __shared__ float fsm[];
    float* sg = fsm;               // 32*128
    float* wt = fsm + 4096;        // 64*128
    float* h  = fsm + 12288;       // 32*128
    float* lg = fsm + 16384;       // 32*9
    int* bi    = (int*)(fsm + 16672);
    int* P     = bi + 32;
    int* flags = bi + 64;
    int tid = threadIdx.x;
    int row0 = blockIdx.x * 32;

    for (int idx = tid; idx < 32*128; idx += 256) {
        int rl = idx >> 7, o = idx & 127;
        int row = row0 + rl;
        int b = row / Nn, n = row % Nn;
        sg[idx] = (float)(g_Sd[(b*Rr + n)*128 + o] * g_a[o] + 38.0 * g_c0[o]);
    }
    if (tid < 32) P[tid] = 0;

    int wrp = tid >> 5, lane = tid & 31;
    int rbase = wrp * 4;
    for (int l = 0; l < Ll; l++) {
        float acc[4][4];
        #pragma unroll
        for (int q = 0; q < 4; q++) {
            float bq = nb1[l*128 + lane*4 + q];
            acc[0][q] = bq; acc[1][q] = bq; acc[2][q] = bq; acc[3][q] = bq;
        }
        for (int tile = 0; tile < 2; tile++) {
            __syncthreads();
            const float* src = g_NW1T + l*16384 + tile*8192;
            for (int i = tid*4; i < 8192; i += 1024)
                *(float4*)(wt + i) = *(const float4*)(src + i);
            __syncthreads();
            #pragma unroll 2
            for (int oo = 0; oo < 64; oo++) {
                float4 w4 = *(const float4*)(wt + oo*128 + lane*4);
                #pragma unroll
                for (int r = 0; r < 4; r++) {
                    float s = sg[(rbase + r)*128 + tile*64 + oo];
                    acc[r][0] = fmaf(s, w4.x, acc[r][0]);
                    acc[r][1] = fmaf(s, w4.y, acc[r][1]);
                    acc[r][2] = fmaf(s, w4.z, acc[r][2]);
                    acc[r][3] = fmaf(s, w4.w, acc[r][3]);
                }
            }
        }
        #pragma unroll
        for (int r = 0; r < 4; r++)
            #pragma unroll
            for (int q = 0; q < 4; q++)
                h[(rbase + r)*128 + lane*4 + q] = tanhf(acc[r][q]);
        __syncthreads();
        for (int pp = tid; pp < 32*NTt; pp += 256) {
            int rl = pp / NTt, t = pp % NTt;
            const float* W2 = nw2 + (l*NTt + t)*128;
            float a = nb2[l*NTt + t];
            for (int c = 0; c < 128; c++) a = fmaf(h[rl*128 + c], W2[c], a);
            lg[rl*NTt + t] = a;
        }
        __syncthreads();
        if (tid < 32) {
            float best = lg[tid*NTt]; int bx = 0;
            #pragma unroll
            for (int t = 1; t < NTt; t++) {
                float v = lg[tid*NTt + t];
                if (v > best) { best = v; bx = t; }
            }
            float second = -1e30f;
            #pragma unroll
            for (int t = 0; t < NTt; t++) {
                float v = lg[tid*NTt + t];
                if (t != bx && v > second) second = v;
            }
            bi[tid] = bx;
            flags[tid] = (best - second < TAU);
        }
        __syncthreads();
        for (int r = 0; r < 4; r++) {
            int rl = rbase + r;
            if (!flags[rl]) continue;
            int row = row0 + rl;
            int b = row / Nn, n = row % Nn;
            const float* W1 = g_NW1T + l*16384;
            double accd[4];
            #pragma unroll
            for (int q = 0; q < 4; q++) accd[q] = (double)nb1[l*128 + lane + 32*q];
            for (int o = 0; o < 128; o++) {
                double gv = g_Sd[(b*Rr + n)*128 + o] * g_a[o] + 38.0 * g_c0[o];
                #pragma unroll
                for (int q = 0; q < 4; q++)
                    accd[q] = fma(gv, (double)W1[o*128 + lane + 32*q], accd[q]);
            }
            double hd[4];
            #pragma unroll
            for (int q = 0; q < 4; q++) hd[q] = tanh(accd[q]);
            double best = -1e300; int bx = 0;
            for (int t = 0; t < NTt; t++) {
                const float* W2 = nw2 + (l*NTt + t)*128;
                double p = 0.0;
                #pragma unroll
                for (int q = 0; q < 4; q++) p = fma(hd[q], (double)W2[lane + 32*q], p);
                #pragma unroll
                for (int s = 16; s > 0; s >>= 1) p += __shfl_down_sync(0xffffffffu, p, s);
                if (lane == 0) {
                    p += (double)nb2[l*NTt + t];
                    if (p > best) { best = p; bx = t; }
                }
            }
            if (lane == 0) bi[rl] = bx;
        }
        __syncthreads();
        if (tid < 32) P[tid] += bi[tid];
    }
    __syncthreads();
    for (int pp = tid; pp < 32*NTt; pp += 256) {
        int rl = pp / NTt, j = pp % NTt;
        int row = row0 + rl;
        int p = P[rl] % NTt;
        out[row*NTt + j] = x_deq[row*NTt + ((j - p + 18) % NTt)];
    }
}

extern "C" void kernel_launch(void* const* d_in, const int* in_sizes, int n_in,
                              void* d_out, int out_size) {
    const float* x       = (const float*)d_in[0];
    const float* adj     = (const float*)d_in[1];
    const float* x_deq   = (const float*)d_in[2];
    const float* adj_deq = (const float*)d_in[3];
    const void*  mn      = d_in[4];
    const void*  me      = d_in[5];
    const int*   isel    = (const int*)d_in[6];
    const float* embw    = (const float*)d_in[7];
    const float* gc1     = (const float*)d_in[8];
    const float* gc2     = (const float*)d_in[9];
    const float* gc3     = (const float*)d_in[10];
    const float* gamma   = (const float*)d_in[11];
    const float* beta    = (const float*)d_in[12];
    const float* nw1     = (const float*)d_in[13];
    const float* nb1     = (const float*)d_in[14];
    const float* nw2     = (const float*)d_in[15];
    const float* nb2     = (const float*)d_in[16];
    const float* ew1     = (const float*)d_in[17];
    const float* eb1     = (const float*)d_in[18];
    const float* ew2     = (const float*)d_in[19];
    const float* eb2     = (const float*)d_in[20];
    float* out = (float*)d_out;

    cudaFuncSetAttribute(k_rgcn, cudaFuncAttributeMaxDynamicSharedMemorySize, 101376);
    cudaFuncSetAttribute(k_edge_flow, cudaFuncAttributeMaxDynamicSharedMemorySize, 99200);
    cudaFuncSetAttribute(k_node_flow, cudaFuncAttributeMaxDynamicSharedMemorySize, 67072);

    k_init<<<1, 128>>>((const unsigned char*)mn);
    k_prep_w<<<2304, 256>>>(gc2, gc3, ew1, nw1);
    k_prep_ps1<<<16, 384>>>(x, embw, gc1);
    k_rgcn<<<BRr, 256, 101120>>>(adj, mn, me, isel);
    k_stats<<<1, 128>>>(gamma, beta);
    k_node_flow<<<19, 256, 67072>>>(x_deq, nb1, nw2, nb2, out);
    k_edge_flow<<<352, 256, 99200>>>(adj_deq, eb1, ew2, eb2, out);
}